// round 12
// baseline (speedup 1.0000x reference)
#include <cuda_runtime.h>
#include <cuda_fp16.h>
#include <math.h>
#include <stdint.h>

constexpr int kT  = 2048;
constexpr int kDm = 1024;
constexpr int kDi = 2048;
constexpr int kNL = 4;
constexpr int kNS = 16;
constexpr int kV  = 32000;
constexpr int kXP = 33;

// Packed fp16 buffers. A tiles: 128 rows x 32 halves (8KB), XOR-swizzled.
// B tiles: R rows x 32 halves (R*64 bytes), R=256 for BN=256 GEMMs, 128 else.
__device__ float  g_x  [kT * kDm];
__device__ __align__(16) __half g_xnh[kT * kDm];
__device__ float  g_xz [kT * 2 * kDi];
__device__ float  g_u  [kT * kDi];
__device__ float  g_xp [kT * kXP];
__device__ __align__(16) __half g_ygh[kT * kDi];
__device__ __align__(16) __half g_wh_in [kNL * 2 * kDi * kDm];
__device__ __align__(16) __half g_wh_out[kNL * kDm * kDi];
__device__ __align__(16) __half g_embh  [kV * kDm];

__device__ __forceinline__ uint32_t smem_u32(const void* p) {
    uint32_t a;
    asm("{ .reg .u64 t; cvta.to.shared.u64 t, %1; cvt.u32.u64 %0, t; }"
        : "=r"(a) : "l"(p));
    return a;
}
#define MBAR_INIT(a, n) \
    asm volatile("mbarrier.init.shared.b64 [%0], %1;" :: "r"(a), "r"(n) : "memory")
#define MBAR_EXPECT_TX(a, tx) \
    asm volatile("mbarrier.arrive.expect_tx.shared.b64 _, [%0], %1;" \
                 :: "r"(a), "r"(tx) : "memory")
#define MBAR_WAIT(a, ph) do {                                                \
    asm volatile(                                                            \
        "{\n\t.reg .pred P;\n"                                               \
        "W%=:\n\t"                                                           \
        "mbarrier.try_wait.parity.acquire.cta.shared::cta.b64 P, [%0], %1, 0x989680;\n\t" \
        "@P bra.uni D%=;\n\t"                                                \
        "bra.uni W%=;\n"                                                     \
        "D%=:\n\t}"                                                          \
        :: "r"(a), "r"(ph) : "memory");                                      \
} while (0)
#define BULK_LD(dst, src, bytes, bar) \
    asm volatile("cp.async.bulk.shared::cluster.global.mbarrier::complete_tx::bytes " \
                 "[%0], [%1], %2, [%3];" \
                 :: "r"(dst), "l"(src), "r"(bytes), "r"(bar) : "memory")

// ---------------------------------------------------------------------------
// Weight pack: f32 [N,K] row-major -> fp16 tiles [nb][kb][R x 32], swizzled.
// ---------------------------------------------------------------------------
template <int R>
__global__ void pack_w_kernel(const float* __restrict__ in,
                              __half* __restrict__ out, int N, int K) {
    long i = (long)blockIdx.x * blockDim.x + threadIdx.x;
    long e = i * 4;
    if (e >= (long)N * K) return;
    int n = (int)(e / K), k = (int)(e % K);
    float4 v = *(const float4*)(in + e);
    int nb = n / R, rr = n % R, kb = k >> 5, col = k & 31;
    int NKt = K >> 5;
    size_t off = ((size_t)(nb * NKt + kb) * (R * 64)) +
                 (uint32_t)((rr * 64 + col * 2) ^ ((rr & 7) << 3));
    __half2 h0 = __floats2half2_rn(v.x, v.y);
    __half2 h1 = __floats2half2_rn(v.z, v.w);
    uint2 u;
    u.x = *(uint32_t*)&h0; u.y = *(uint32_t*)&h1;
    *(uint2*)((char*)out + off) = u;
}

__global__ void embed_kernel(const int* __restrict__ idx,
                             const float* __restrict__ emb) {
    int t = blockIdx.x;
    int row = idx[t];
    ((float4*)(g_x + (size_t)t * kDm))[threadIdx.x] =
        ((const float4*)(emb + (size_t)row * kDm))[threadIdx.x];
}

__global__ void rmsnorm_kernel(const float* __restrict__ in,
                               const float* __restrict__ w,
                               __half* __restrict__ out) {
    __shared__ float red[8];
    __shared__ float s_scale;
    int t = blockIdx.x;
    float4 v = ((const float4*)(in + (size_t)t * kDm))[threadIdx.x];
    float ss = v.x * v.x + v.y * v.y + v.z * v.z + v.w * v.w;
    #pragma unroll
    for (int o = 16; o; o >>= 1) ss += __shfl_xor_sync(0xffffffffu, ss, o);
    int warp = threadIdx.x >> 5, lane = threadIdx.x & 31;
    if (lane == 0) red[warp] = ss;
    __syncthreads();
    if (threadIdx.x == 0) {
        float s = 0.f;
        #pragma unroll
        for (int i = 0; i < 8; i++) s += red[i];
        s_scale = rsqrtf(s / (float)kDm + 1e-5f);
    }
    __syncthreads();
    float sc = s_scale;
    float4 wv = ((const float4*)w)[threadIdx.x];
    __half2 h0 = __floats2half2_rn(v.x * sc * wv.x, v.y * sc * wv.y);
    __half2 h1 = __floats2half2_rn(v.z * sc * wv.z, v.w * sc * wv.w);
    int d0 = threadIdx.x * 4;
    int tb = t >> 7, r = t & 127, kb = d0 >> 5, col = d0 & 31;
    size_t off = ((size_t)(tb * (kDm >> 5) + kb) * 8192) +
                 (uint32_t)((r * 64 + col * 2) ^ ((r & 7) << 3));
    uint2 u;
    u.x = *(uint32_t*)&h0; u.y = *(uint32_t*)&h1;
    *(uint2*)((char*)out + off) = u;
}

// ---------------------------------------------------------------------------
// fp16 mma.sync NT GEMM with cp.async.bulk pipeline (R6/R11, best known).
// ---------------------------------------------------------------------------
template <int BN, int THREADS>
__global__ __launch_bounds__(THREADS, (BN == 128) ? 2 : 1)
void gemm_bulk(const __half* __restrict__ Ap, const __half* __restrict__ Bp,
               float* __restrict__ C, int M, int N, int K, int acc_flag) {
    constexpr int S  = 3;
    constexpr int SB = 8192 + BN * 64;
    constexpr int WNN = BN / 32;
    extern __shared__ char sm[];
    uint32_t sb = smem_u32(sm);

    int tid = threadIdx.x, lane = tid & 31, wrp = tid >> 5;
    int wm = wrp / WNN, wn = wrp % WNN;
    int l2 = lane & 3, l4 = lane >> 2;
    int NKt = K >> 5;

    const char* gA = (const char*)Ap + (size_t)blockIdx.y * NKt * 8192;
    const char* gB = (const char*)Bp + (size_t)blockIdx.x * NKt * (BN * 64);

    if (tid == 0) {
        #pragma unroll
        for (int s = 0; s < S; s++) MBAR_INIT(sb + 8 * s, 1);
    }
    __syncthreads();

    auto issue = [&](int j) {
        uint32_t bar = sb + 8 * (j % S);
        uint32_t dA  = sb + 1024 + (j % S) * SB;
        MBAR_EXPECT_TX(bar, (uint32_t)SB);
        BULK_LD(dA, gA + (size_t)j * 8192, 8192u, bar);
        BULK_LD(dA + 8192, gB + (size_t)j * (BN * 64), (uint32_t)(BN * 64), bar);
    };
    if (tid == 0) { issue(0); issue(1); }

    float acc[4][4][4];
    #pragma unroll
    for (int i = 0; i < 4; i++)
        #pragma unroll
        for (int j = 0; j < 4; j++)
            #pragma unroll
            for (int r = 0; r < 4; r++) acc[i][j][r] = 0.f;

    uint32_t cx[4];
    #pragma unroll
    for (int p = 0; p < 4; p++) cx[p] = (uint32_t)((p * 16 + 4 * l2) ^ (l4 << 3));

    for (int ks = 0; ks < NKt; ks++) {
        MBAR_WAIT(sb + 8 * (ks % S), (ks / S) & 1);

        const char* As = sm + 1024 + (ks % S) * SB;
        const char* Bs = As + 8192;
        #pragma unroll
        for (int ph = 0; ph < 2; ph++) {
            uint32_t af[4][4];
            uint32_t bf[4][2];
            #pragma unroll
            for (int mi = 0; mi < 4; mi++) {
                uint32_t rb = (uint32_t)(wm * 64 + mi * 16 + l4) * 64;
                af[mi][0] = *(const uint32_t*)(As + rb       + cx[ph * 2]);
                af[mi][1] = *(const uint32_t*)(As + rb + 512 + cx[ph * 2]);
                af[mi][2] = *(const uint32_t*)(As + rb       + cx[ph * 2 + 1]);
                af[mi][3] = *(const uint32_t*)(As + rb + 512 + cx[ph * 2 + 1]);
            }
            #pragma unroll
            for (int ni = 0; ni < 4; ni++) {
                uint32_t rb = (uint32_t)(wn * 32 + ni * 8 + l4) * 64;
                bf[ni][0] = *(const uint32_t*)(Bs + rb + cx[ph * 2]);
                bf[ni][1] = *(const uint32_t*)(Bs + rb + cx[ph * 2 + 1]);
            }
            #pragma unroll
            for (int mi = 0; mi < 4; mi++)
                #pragma unroll
                for (int ni = 0; ni < 4; ni++) {
                    asm volatile(
                        "mma.sync.aligned.m16n8k16.row.col.f32.f16.f16.f32 "
                        "{%0,%1,%2,%3}, {%4,%5,%6,%7}, {%8,%9}, {%0,%1,%2,%3};"
                        : "+f"(acc[mi][ni][0]), "+f"(acc[mi][ni][1]),
                          "+f"(acc[mi][ni][2]), "+f"(acc[mi][ni][3])
                        : "r"(af[mi][0]), "r"(af[mi][1]),
                          "r"(af[mi][2]), "r"(af[mi][3]),
                          "r"(bf[ni][0]), "r"(bf[ni][1]));
                }
        }
        __syncthreads();
        if (tid == 0 && ks + 2 < NKt) issue(ks + 2);
    }

    #pragma unroll
    for (int mi = 0; mi < 4; mi++) {
        int row0 = blockIdx.y * 128 + wm * 64 + mi * 16 + l4;
        #pragma unroll
        for (int ni = 0; ni < 4; ni++) {
            int col0 = blockIdx.x * BN + wn * 32 + ni * 8 + 2 * l2;
            float2* p0 = (float2*)(C + (size_t)row0 * N + col0);
            float2* p1 = (float2*)(C + (size_t)(row0 + 8) * N + col0);
            if (acc_flag) {
                float2 v0 = *p0, v1 = *p1;
                v0.x += acc[mi][ni][0]; v0.y += acc[mi][ni][1];
                v1.x += acc[mi][ni][2]; v1.y += acc[mi][ni][3];
                *p0 = v0; *p1 = v1;
            } else {
                *p0 = make_float2(acc[mi][ni][0], acc[mi][ni][1]);
                *p1 = make_float2(acc[mi][ni][2], acc[mi][ni][3]);
            }
        }
    }
}

constexpr int SMEM_BN256 = 1024 + 3 * (8192 + 256 * 64);
constexpr int SMEM_BN128 = 1024 + 3 * (8192 + 128 * 64);

// ---------------------------------------------------------------------------
// Fused causal conv(K=4)+silu + x_proj for 8 tokens per block.
// u computed from xz directly into smem (and gmem for the scan), then
// xproj dot-products read u from smem. Eliminates the u gmem readback.
// ---------------------------------------------------------------------------
constexpr int CX_SMEM = 8 * kDi * 4;   // 65536

__global__ __launch_bounds__(256)
void convxproj_kernel(const float* __restrict__ cw,
                      const float* __restrict__ cb,
                      const float* __restrict__ W) {
    extern __shared__ float su[];      // [8][2048]
    int t0 = blockIdx.x * 8;
    const int stride = 2 * kDi;

    // conv + silu: each thread handles 8 channels x 8 timesteps
    #pragma unroll
    for (int j = 0; j < 8; j++) {
        int c = threadIdx.x + 256 * j;
        float4 wv = ((const float4*)cw)[c];
        float b = cb[c];
        float x0 = (t0 >= 3) ? g_xz[(size_t)(t0 - 3) * stride + c] : 0.f;
        float x1 = (t0 >= 2) ? g_xz[(size_t)(t0 - 2) * stride + c] : 0.f;
        float x2 = (t0 >= 1) ? g_xz[(size_t)(t0 - 1) * stride + c] : 0.f;
        #pragma unroll
        for (int i = 0; i < 8; i++) {
            float cur = g_xz[(size_t)(t0 + i) * stride + c];
            float s = b + wv.x * x0 + wv.y * x1 + wv.z * x2 + wv.w * cur;
            float u = s / (1.f + __expf(-s));
            su[i * kDi + c] = u;
            g_u[(size_t)(t0 + i) * kDi + c] = u;
            x0 = x1; x1 = x2; x2 = cur;
        }
    }
    __syncthreads();

    // xproj: W streamed once per block, 8-token reuse from smem
    int warp = threadIdx.x >> 5, lane = threadIdx.x & 31;
    for (int j = warp; j < kXP; j += 8) {
        const float4* wr = (const float4*)(W + (size_t)j * kDi);
        float acc[8];
        #pragma unroll
        for (int r = 0; r < 8; r++) acc[r] = 0.f;
        #pragma unroll 4
        for (int k = lane; k < kDi / 4; k += 32) {
            float4 bv = wr[k];
            #pragma unroll
            for (int r = 0; r < 8; r++) {
                float4 a = ((const float4*)(su + r * kDi))[k];
                acc[r] += a.x * bv.x + a.y * bv.y + a.z * bv.z + a.w * bv.w;
            }
        }
        #pragma unroll
        for (int r = 0; r < 8; r++) {
            float s = acc[r];
            #pragma unroll
            for (int o = 16; o; o >>= 1) s += __shfl_xor_sync(0xffffffffu, s, o);
            if (lane == 0) g_xp[(t0 + r) * kXP + j] = s;
        }
    }
}

// ---------------------------------------------------------------------------
// Selective scan -> packed swizzled fp16
// ---------------------------------------------------------------------------
__global__ void scan_kernel(const float* __restrict__ A_log,
                            const float* __restrict__ dtw_,
                            const float* __restrict__ dtb_,
                            const float* __restrict__ Dp_) {
    int tid = threadIdx.x;
    int n = tid & 15;
    int g = tid >> 4;
    int d = blockIdx.x * 8 + g;
    float a   = -expf(A_log[(size_t)d * kNS + n]);
    float dtw = dtw_[d];
    float dtb = dtb_[d];
    float Dp  = Dp_[d];
    int kb = d >> 5, col = d & 31;
    float h = 0.f;
    for (int t = 0; t < kT; t++) {
        const float* xpr = g_xp + (size_t)t * kXP;
        float xv = xpr[0] * dtw + dtb;
        float dt = (xv > 20.f) ? xv : log1pf(__expf(xv));
        float Bn = xpr[1 + n];
        float Cn = xpr[17 + n];
        float ut = g_u[(size_t)t * kDi + d];
        float dA = __expf(dt * a);
        h = dA * h + (dt * ut) * Bn;
        float p = h * Cn;
        p += __shfl_xor_sync(0xffffffffu, p, 8);
        p += __shfl_xor_sync(0xffffffffu, p, 4);
        p += __shfl_xor_sync(0xffffffffu, p, 2);
        p += __shfl_xor_sync(0xffffffffu, p, 1);
        if (n == 0) {
            float z = g_xz[(size_t)t * (2 * kDi) + kDi + d];
            float y = p + ut * Dp;
            int tb = t >> 7, r = t & 127;
            size_t off = ((size_t)(tb * (kDi >> 5) + kb) * 8192) +
                         (uint32_t)((r * 64 + col * 2) ^ ((r & 7) << 3));
            *(__half*)((char*)g_ygh + off) =
                __float2half_rn(y * (z / (1.f + __expf(-z))));
        }
    }
}

// ---------------------------------------------------------------------------
extern "C" void kernel_launch(void* const* d_in, const int* in_sizes, int n_in,
                              void* d_out, int out_size) {
    const int*   idx        = (const int*)  d_in[0];
    const float* emb        = (const float*)d_in[1];
    const float* norm_w     = (const float*)d_in[2];
    const float* in_proj_w  = (const float*)d_in[3];
    const float* conv_w     = (const float*)d_in[4];
    const float* conv_b     = (const float*)d_in[5];
    const float* x_proj_w   = (const float*)d_in[6];
    const float* dt_proj_w  = (const float*)d_in[7];
    const float* dt_proj_b  = (const float*)d_in[8];
    const float* A_log      = (const float*)d_in[9];
    const float* D_param    = (const float*)d_in[10];
    const float* out_proj_w = (const float*)d_in[11];
    const float* norm_f_w   = (const float*)d_in[12];
    float* out = (float*)d_out;

    float *x, *xz;
    __half *xnh, *ygh, *wh_in, *wh_out, *embh;
    cudaGetSymbolAddress((void**)&x,      g_x);
    cudaGetSymbolAddress((void**)&xnh,    g_xnh);
    cudaGetSymbolAddress((void**)&xz,     g_xz);
    cudaGetSymbolAddress((void**)&ygh,    g_ygh);
    cudaGetSymbolAddress((void**)&wh_in,  g_wh_in);
    cudaGetSymbolAddress((void**)&wh_out, g_wh_out);
    cudaGetSymbolAddress((void**)&embh,   g_embh);

    cudaFuncSetAttribute(gemm_bulk<256, 512>,
                         cudaFuncAttributeMaxDynamicSharedMemorySize, SMEM_BN256);
    cudaFuncSetAttribute(gemm_bulk<128, 256>,
                         cudaFuncAttributeMaxDynamicSharedMemorySize, SMEM_BN128);
    cudaFuncSetAttribute(convxproj_kernel,
                         cudaFuncAttributeMaxDynamicSharedMemorySize, CX_SMEM);

    long n1 = (long)kNL * 2 * kDi * kDm / 4;
    long n2 = (long)kNL * kDm * kDi / 4;
    long n3 = (long)kV * kDm / 4;

    // Launch order puts gemm_bulk<256> at slot 4 (ncu capture window).
    pack_w_kernel<256><<<(int)((n1 + 255) / 256), 256>>>(in_proj_w,  wh_in,
                                                         kNL * 2 * kDi, kDm);   // 1
    embed_kernel<<<kT, 256>>>(idx, emb);                                        // 2
    rmsnorm_kernel<<<kT, 256>>>(x, norm_w, xnh);                                // 3
    gemm_bulk<256, 512><<<dim3(2 * kDi / 256, kT / 128), 512, SMEM_BN256>>>(    // 4
        xnh, wh_in, xz, kT, 2 * kDi, kDm, 0);
    pack_w_kernel<128><<<(int)((n2 + 255) / 256), 256>>>(out_proj_w, wh_out,
                                                         kNL * kDm, kDi);       // 5
    pack_w_kernel<256><<<(int)((n3 + 255) / 256), 256>>>(emb,        embh,
                                                         kV, kDm);              // 6

    for (int l = 0; l < kNL; l++) {
        if (l > 0) {
            rmsnorm_kernel<<<kT, 256>>>(x, norm_w + (size_t)l * kDm, xnh);
            gemm_bulk<256, 512><<<dim3(2 * kDi / 256, kT / 128), 512, SMEM_BN256>>>(
                xnh, wh_in + (size_t)l * 2 * kDi * kDm, xz, kT, 2 * kDi, kDm, 0);
        }
        convxproj_kernel<<<kT / 8, 256, CX_SMEM>>>(
            conv_w + (size_t)l * kDi * 4, conv_b + (size_t)l * kDi,
            x_proj_w + (size_t)l * kXP * kDi);
        scan_kernel<<<kDi / 8, 128>>>(
            A_log + (size_t)l * kDi * kNS,
            dt_proj_w + (size_t)l * kDi,
            dt_proj_b + (size_t)l * kDi,
            D_param + (size_t)l * kDi);
        gemm_bulk<128, 256><<<dim3(kDm / 128, kT / 128), 256, SMEM_BN128>>>(
            ygh, wh_out + (size_t)l * kDm * kDi, x, kT, kDm, kDi, 1);
    }

    rmsnorm_kernel<<<kT, 256>>>(x, norm_f_w, xnh);
    gemm_bulk<256, 512><<<dim3(kV / 256, kT / 128), 512, SMEM_BN256>>>(
        xnh, embh, out, kT, kV, kDm, 0);
}

// round 13
// speedup vs baseline: 2.6568x; 2.6568x over previous
#include <cuda_runtime.h>
#include <cuda_fp16.h>
#include <math.h>
#include <stdint.h>

constexpr int kT  = 2048;
constexpr int kDm = 1024;
constexpr int kDi = 2048;
constexpr int kNL = 4;
constexpr int kNS = 16;
constexpr int kV  = 32000;
constexpr int kXP = 33;

// Packed fp16 buffers. A tiles: 128 rows x 32 halves (8KB), XOR-swizzled.
// B tiles: R rows x 32 halves (R*64 bytes), R=256 for BN=256 GEMMs, 128 else.
__device__ float  g_x  [kT * kDm];
__device__ __align__(16) __half g_xnh[kT * kDm];
__device__ float  g_xz [kT * 2 * kDi];
__device__ float  g_u  [kT * kDi];
__device__ float  g_xp [kT * kXP];
__device__ __align__(16) __half g_ygh[kT * kDi];
__device__ __align__(16) __half g_wh_in [kNL * 2 * kDi * kDm];
__device__ __align__(16) __half g_wh_out[kNL * kDm * kDi];
__device__ __align__(16) __half g_embh  [kV * kDm];

__device__ __forceinline__ uint32_t smem_u32(const void* p) {
    uint32_t a;
    asm("{ .reg .u64 t; cvta.to.shared.u64 t, %1; cvt.u32.u64 %0, t; }"
        : "=r"(a) : "l"(p));
    return a;
}
#define MBAR_INIT(a, n) \
    asm volatile("mbarrier.init.shared.b64 [%0], %1;" :: "r"(a), "r"(n) : "memory")
#define MBAR_EXPECT_TX(a, tx) \
    asm volatile("mbarrier.arrive.expect_tx.shared.b64 _, [%0], %1;" \
                 :: "r"(a), "r"(tx) : "memory")
#define MBAR_WAIT(a, ph) do {                                                \
    asm volatile(                                                            \
        "{\n\t.reg .pred P;\n"                                               \
        "W%=:\n\t"                                                           \
        "mbarrier.try_wait.parity.acquire.cta.shared::cta.b64 P, [%0], %1, 0x989680;\n\t" \
        "@P bra.uni D%=;\n\t"                                                \
        "bra.uni W%=;\n"                                                     \
        "D%=:\n\t}"                                                          \
        :: "r"(a), "r"(ph) : "memory");                                      \
} while (0)
#define BULK_LD(dst, src, bytes, bar) \
    asm volatile("cp.async.bulk.shared::cluster.global.mbarrier::complete_tx::bytes " \
                 "[%0], [%1], %2, [%3];" \
                 :: "r"(dst), "l"(src), "r"(bytes), "r"(bar) : "memory")
#define CP4(dst, src) \
    asm volatile("cp.async.ca.shared.global [%0], [%1], 4;" \
                 :: "r"(dst), "l"(src) : "memory")

// ---------------------------------------------------------------------------
// Weight pack: f32 [N,K] row-major -> fp16 tiles [nb][kb][R x 32], swizzled.
// ---------------------------------------------------------------------------
template <int R>
__global__ void pack_w_kernel(const float* __restrict__ in,
                              __half* __restrict__ out, int N, int K) {
    long i = (long)blockIdx.x * blockDim.x + threadIdx.x;
    long e = i * 4;
    if (e >= (long)N * K) return;
    int n = (int)(e / K), k = (int)(e % K);
    float4 v = *(const float4*)(in + e);
    int nb = n / R, rr = n % R, kb = k >> 5, col = k & 31;
    int NKt = K >> 5;
    size_t off = ((size_t)(nb * NKt + kb) * (R * 64)) +
                 (uint32_t)((rr * 64 + col * 2) ^ ((rr & 7) << 3));
    __half2 h0 = __floats2half2_rn(v.x, v.y);
    __half2 h1 = __floats2half2_rn(v.z, v.w);
    uint2 u;
    u.x = *(uint32_t*)&h0; u.y = *(uint32_t*)&h1;
    *(uint2*)((char*)out + off) = u;
}

__global__ void embed_kernel(const int* __restrict__ idx,
                             const float* __restrict__ emb) {
    int t = blockIdx.x;
    int row = idx[t];
    ((float4*)(g_x + (size_t)t * kDm))[threadIdx.x] =
        ((const float4*)(emb + (size_t)row * kDm))[threadIdx.x];
}

__global__ void rmsnorm_kernel(const float* __restrict__ in,
                               const float* __restrict__ w,
                               __half* __restrict__ out) {
    __shared__ float red[8];
    __shared__ float s_scale;
    int t = blockIdx.x;
    float4 v = ((const float4*)(in + (size_t)t * kDm))[threadIdx.x];
    float ss = v.x * v.x + v.y * v.y + v.z * v.z + v.w * v.w;
    #pragma unroll
    for (int o = 16; o; o >>= 1) ss += __shfl_xor_sync(0xffffffffu, ss, o);
    int warp = threadIdx.x >> 5, lane = threadIdx.x & 31;
    if (lane == 0) red[warp] = ss;
    __syncthreads();
    if (threadIdx.x == 0) {
        float s = 0.f;
        #pragma unroll
        for (int i = 0; i < 8; i++) s += red[i];
        s_scale = rsqrtf(s / (float)kDm + 1e-5f);
    }
    __syncthreads();
    float sc = s_scale;
    float4 wv = ((const float4*)w)[threadIdx.x];
    __half2 h0 = __floats2half2_rn(v.x * sc * wv.x, v.y * sc * wv.y);
    __half2 h1 = __floats2half2_rn(v.z * sc * wv.z, v.w * sc * wv.w);
    int d0 = threadIdx.x * 4;
    int tb = t >> 7, r = t & 127, kb = d0 >> 5, col = d0 & 31;
    size_t off = ((size_t)(tb * (kDm >> 5) + kb) * 8192) +
                 (uint32_t)((r * 64 + col * 2) ^ ((r & 7) << 3));
    uint2 u;
    u.x = *(uint32_t*)&h0; u.y = *(uint32_t*)&h1;
    *(uint2*)((char*)out + off) = u;
}

// ---------------------------------------------------------------------------
// fp16 mma.sync NT GEMM with cp.async.bulk pipeline (R6/R11, best known).
// ---------------------------------------------------------------------------
template <int BN, int THREADS>
__global__ __launch_bounds__(THREADS, (BN == 128) ? 2 : 1)
void gemm_bulk(const __half* __restrict__ Ap, const __half* __restrict__ Bp,
               float* __restrict__ C, int M, int N, int K, int acc_flag) {
    constexpr int S  = 3;
    constexpr int SB = 8192 + BN * 64;
    constexpr int WNN = BN / 32;
    extern __shared__ char sm[];
    uint32_t sb = smem_u32(sm);

    int tid = threadIdx.x, lane = tid & 31, wrp = tid >> 5;
    int wm = wrp / WNN, wn = wrp % WNN;
    int l2 = lane & 3, l4 = lane >> 2;
    int NKt = K >> 5;

    const char* gA = (const char*)Ap + (size_t)blockIdx.y * NKt * 8192;
    const char* gB = (const char*)Bp + (size_t)blockIdx.x * NKt * (BN * 64);

    if (tid == 0) {
        #pragma unroll
        for (int s = 0; s < S; s++) MBAR_INIT(sb + 8 * s, 1);
    }
    __syncthreads();

    auto issue = [&](int j) {
        uint32_t bar = sb + 8 * (j % S);
        uint32_t dA  = sb + 1024 + (j % S) * SB;
        MBAR_EXPECT_TX(bar, (uint32_t)SB);
        BULK_LD(dA, gA + (size_t)j * 8192, 8192u, bar);
        BULK_LD(dA + 8192, gB + (size_t)j * (BN * 64), (uint32_t)(BN * 64), bar);
    };
    if (tid == 0) { issue(0); issue(1); }

    float acc[4][4][4];
    #pragma unroll
    for (int i = 0; i < 4; i++)
        #pragma unroll
        for (int j = 0; j < 4; j++)
            #pragma unroll
            for (int r = 0; r < 4; r++) acc[i][j][r] = 0.f;

    uint32_t cx[4];
    #pragma unroll
    for (int p = 0; p < 4; p++) cx[p] = (uint32_t)((p * 16 + 4 * l2) ^ (l4 << 3));

    for (int ks = 0; ks < NKt; ks++) {
        MBAR_WAIT(sb + 8 * (ks % S), (ks / S) & 1);

        const char* As = sm + 1024 + (ks % S) * SB;
        const char* Bs = As + 8192;
        #pragma unroll
        for (int ph = 0; ph < 2; ph++) {
            uint32_t af[4][4];
            uint32_t bf[4][2];
            #pragma unroll
            for (int mi = 0; mi < 4; mi++) {
                uint32_t rb = (uint32_t)(wm * 64 + mi * 16 + l4) * 64;
                af[mi][0] = *(const uint32_t*)(As + rb       + cx[ph * 2]);
                af[mi][1] = *(const uint32_t*)(As + rb + 512 + cx[ph * 2]);
                af[mi][2] = *(const uint32_t*)(As + rb       + cx[ph * 2 + 1]);
                af[mi][3] = *(const uint32_t*)(As + rb + 512 + cx[ph * 2 + 1]);
            }
            #pragma unroll
            for (int ni = 0; ni < 4; ni++) {
                uint32_t rb = (uint32_t)(wn * 32 + ni * 8 + l4) * 64;
                bf[ni][0] = *(const uint32_t*)(Bs + rb + cx[ph * 2]);
                bf[ni][1] = *(const uint32_t*)(Bs + rb + cx[ph * 2 + 1]);
            }
            #pragma unroll
            for (int mi = 0; mi < 4; mi++)
                #pragma unroll
                for (int ni = 0; ni < 4; ni++) {
                    asm volatile(
                        "mma.sync.aligned.m16n8k16.row.col.f32.f16.f16.f32 "
                        "{%0,%1,%2,%3}, {%4,%5,%6,%7}, {%8,%9}, {%0,%1,%2,%3};"
                        : "+f"(acc[mi][ni][0]), "+f"(acc[mi][ni][1]),
                          "+f"(acc[mi][ni][2]), "+f"(acc[mi][ni][3])
                        : "r"(af[mi][0]), "r"(af[mi][1]),
                          "r"(af[mi][2]), "r"(af[mi][3]),
                          "r"(bf[ni][0]), "r"(bf[ni][1]));
                }
        }
        __syncthreads();
        if (tid == 0 && ks + 2 < NKt) issue(ks + 2);
    }

    #pragma unroll
    for (int mi = 0; mi < 4; mi++) {
        int row0 = blockIdx.y * 128 + wm * 64 + mi * 16 + l4;
        #pragma unroll
        for (int ni = 0; ni < 4; ni++) {
            int col0 = blockIdx.x * BN + wn * 32 + ni * 8 + 2 * l2;
            float2* p0 = (float2*)(C + (size_t)row0 * N + col0);
            float2* p1 = (float2*)(C + (size_t)(row0 + 8) * N + col0);
            if (acc_flag) {
                float2 v0 = *p0, v1 = *p1;
                v0.x += acc[mi][ni][0]; v0.y += acc[mi][ni][1];
                v1.x += acc[mi][ni][2]; v1.y += acc[mi][ni][3];
                *p0 = v0; *p1 = v1;
            } else {
                *p0 = make_float2(acc[mi][ni][0], acc[mi][ni][1]);
                *p1 = make_float2(acc[mi][ni][2], acc[mi][ni][3]);
            }
        }
    }
}

constexpr int SMEM_BN256 = 1024 + 3 * (8192 + 256 * 64);
constexpr int SMEM_BN128 = 1024 + 3 * (8192 + 128 * 64);

// ---------------------------------------------------------------------------
// Causal depthwise conv (K=4) + bias + silu; rolling window, 8 t per thread.
// ---------------------------------------------------------------------------
__global__ void conv_silu8_kernel(const float* __restrict__ cw,
                                  const float* __restrict__ cb) {
    int c  = blockIdx.x * 256 + threadIdx.x;
    int t0 = blockIdx.y * 8;
    const int stride = 2 * kDi;
    float w0 = cw[c * 4 + 0], w1 = cw[c * 4 + 1];
    float w2 = cw[c * 4 + 2], w3 = cw[c * 4 + 3];
    float b  = cb[c];
    float x0 = (t0 >= 3) ? g_xz[(size_t)(t0 - 3) * stride + c] : 0.f;
    float x1 = (t0 >= 2) ? g_xz[(size_t)(t0 - 2) * stride + c] : 0.f;
    float x2 = (t0 >= 1) ? g_xz[(size_t)(t0 - 1) * stride + c] : 0.f;
    #pragma unroll
    for (int i = 0; i < 8; i++) {
        float cur = g_xz[(size_t)(t0 + i) * stride + c];
        float s = b + w0 * x0 + w1 * x1 + w2 * x2 + w3 * cur;
        g_u[(size_t)(t0 + i) * kDi + c] = s / (1.f + __expf(-s));
        x0 = x1; x1 = x2; x2 = cur;
    }
}

// ---------------------------------------------------------------------------
// x_proj, 8 tokens per block: u rows staged in smem, W streamed once/block.
// ---------------------------------------------------------------------------
constexpr int XP_SMEM = 8 * kDi * 4;   // 65536

__global__ __launch_bounds__(256)
void xproj8_kernel(const float* __restrict__ W) {
    extern __shared__ float su[];      // [8][2048]
    int t0 = blockIdx.x * 8;
    const float4* usrc = (const float4*)(g_u + (size_t)t0 * kDi);
    for (int i = threadIdx.x; i < 8 * kDi / 4; i += 256)
        ((float4*)su)[i] = usrc[i];
    __syncthreads();

    int warp = threadIdx.x >> 5, lane = threadIdx.x & 31;
    for (int j = warp; j < kXP; j += 8) {
        const float4* wr = (const float4*)(W + (size_t)j * kDi);
        float acc[8];
        #pragma unroll
        for (int r = 0; r < 8; r++) acc[r] = 0.f;
        #pragma unroll 4
        for (int k = lane; k < kDi / 4; k += 32) {
            float4 bv = wr[k];
            #pragma unroll
            for (int r = 0; r < 8; r++) {
                float4 a = ((const float4*)(su + r * kDi))[k];
                acc[r] += a.x * bv.x + a.y * bv.y + a.z * bv.z + a.w * bv.w;
            }
        }
        #pragma unroll
        for (int r = 0; r < 8; r++) {
            float s = acc[r];
            #pragma unroll
            for (int o = 16; o; o >>= 1) s += __shfl_xor_sync(0xffffffffu, s, o);
            if (lane == 0) g_xp[(t0 + r) * kXP + j] = s;
        }
    }
}

// ---------------------------------------------------------------------------
// Selective scan v2: chunked smem staging (cp.async double buffer) + per-chunk
// derived precompute (softplus/silu off the serial path).
// Block = 128 threads = 8 channels x 16 states. Grid = kDi/8 = 256.
// ---------------------------------------------------------------------------
__global__ __launch_bounds__(128)
void scan2_kernel(const float* __restrict__ A_log,
                  const float* __restrict__ dtw_,
                  const float* __restrict__ dtb_,
                  const float* __restrict__ Dp_) {
    __shared__ float sxp [2][32][32];   // [i][0..15]=B, [16..31]=C
    __shared__ float sraw[2][32];       // xp[t][0]
    __shared__ float su_ [2][32][8];
    __shared__ float sz_ [2][32][8];
    __shared__ float sdt [32][8];
    __shared__ float sdtu[32][8];
    __shared__ float szs [32][8];
    __shared__ float sw2 [32][8];

    int tid = threadIdx.x;
    int d0  = blockIdx.x * 8;
    int n   = tid & 15;        // state index
    int dgl = tid >> 4;        // channel group 0..7
    int d   = d0 + dgl;
    float a = -expf(A_log[(size_t)d * kNS + n]);

    // per-thread derive params (dg = tid & 7, used for both derive elements)
    int dgd = tid & 7;
    float p_dtw = dtw_[d0 + dgd];
    float p_dtb = dtb_[d0 + dgd];
    float p_Dp  = Dp_[d0 + dgd];

    // store address precompute (lane n==0 only uses it)
    int kbq = d >> 5, colq = d & 31;

    auto issue = [&](int k) {
        int b = k & 1;
        int t0 = k * 32;
        // xp cols 1..32 (B|C)
        int i = tid >> 2, j0 = (tid & 3) * 8;
        const float* src = g_xp + (size_t)(t0 + i) * kXP + 1 + j0;
        uint32_t dst = smem_u32(&sxp[b][i][j0]);
        #pragma unroll
        for (int jj = 0; jj < 8; jj++) CP4(dst + 4 * jj, src + jj);
        // xp col 0
        if (tid < 32)
            CP4(smem_u32(&sraw[b][tid]), g_xp + (size_t)(t0 + tid) * kXP);
        // u, z
        #pragma unroll
        for (int q = 0; q < 2; q++) {
            int e = tid + q * 128;
            int i2 = e >> 3, dg = e & 7;
            CP4(smem_u32(&su_[b][i2][dg]),
                g_u + (size_t)(t0 + i2) * kDi + d0 + dg);
            CP4(smem_u32(&sz_[b][i2][dg]),
                g_xz + (size_t)(t0 + i2) * (2 * kDi) + kDi + d0 + dg);
        }
        asm volatile("cp.async.commit_group;" ::: "memory");
    };

    issue(0);

    float h = 0.f;
    for (int k = 0; k < kT / 32; k++) {
        int b = k & 1;
        asm volatile("cp.async.wait_group 0;" ::: "memory");
        __syncthreads();
        if (k + 1 < kT / 32) issue(k + 1);

        // derive: 2 (i,dg) pairs per thread
        #pragma unroll
        for (int q = 0; q < 2; q++) {
            int e = tid + q * 128;
            int i2 = e >> 3;
            float xv = fmaf(sraw[b][i2], p_dtw, p_dtb);
            float dt = (xv > 20.f) ? xv : log1pf(__expf(xv));
            float u  = su_[b][i2][dgd];
            float z  = sz_[b][i2][dgd];
            float zs = z / (1.f + __expf(-z));
            sdt [i2][dgd] = dt;
            sdtu[i2][dgd] = dt * u;
            szs [i2][dgd] = zs;
            sw2 [i2][dgd] = u * p_Dp * zs;
        }
        __syncthreads();

        int tbase = k * 32;
        #pragma unroll 8
        for (int i = 0; i < 32; i++) {
            float Bn  = sxp[b][i][n];
            float Cn  = sxp[b][i][16 + n];
            float dt  = sdt[i][dgl];
            float dtu = sdtu[i][dgl];
            float dA  = __expf(dt * a);
            h = fmaf(dA, h, dtu * Bn);
            float p = h * Cn;
            p += __shfl_xor_sync(0xffffffffu, p, 8);
            p += __shfl_xor_sync(0xffffffffu, p, 4);
            p += __shfl_xor_sync(0xffffffffu, p, 2);
            p += __shfl_xor_sync(0xffffffffu, p, 1);
            if (n == 0) {
                float y = fmaf(p, szs[i][dgl], sw2[i][dgl]);
                int t = tbase + i;
                int tb = t >> 7, r = t & 127;
                size_t off = ((size_t)(tb * (kDi >> 5) + kbq) * 8192) +
                             (uint32_t)((r * 64 + colq * 2) ^ ((r & 7) << 3));
                *(__half*)((char*)g_ygh + off) = __float2half_rn(y);
            }
        }
    }
}

// ---------------------------------------------------------------------------
extern "C" void kernel_launch(void* const* d_in, const int* in_sizes, int n_in,
                              void* d_out, int out_size) {
    const int*   idx        = (const int*)  d_in[0];
    const float* emb        = (const float*)d_in[1];
    const float* norm_w     = (const float*)d_in[2];
    const float* in_proj_w  = (const float*)d_in[3];
    const float* conv_w     = (const float*)d_in[4];
    const float* conv_b     = (const float*)d_in[5];
    const float* x_proj_w   = (const float*)d_in[6];
    const float* dt_proj_w  = (const float*)d_in[7];
    const float* dt_proj_b  = (const float*)d_in[8];
    const float* A_log      = (const float*)d_in[9];
    const float* D_param    = (const float*)d_in[10];
    const float* out_proj_w = (const float*)d_in[11];
    const float* norm_f_w   = (const float*)d_in[12];
    float* out = (float*)d_out;

    float *x, *xz;
    __half *xnh, *ygh, *wh_in, *wh_out, *embh;
    cudaGetSymbolAddress((void**)&x,      g_x);
    cudaGetSymbolAddress((void**)&xnh,    g_xnh);
    cudaGetSymbolAddress((void**)&xz,     g_xz);
    cudaGetSymbolAddress((void**)&ygh,    g_ygh);
    cudaGetSymbolAddress((void**)&wh_in,  g_wh_in);
    cudaGetSymbolAddress((void**)&wh_out, g_wh_out);
    cudaGetSymbolAddress((void**)&embh,   g_embh);

    cudaFuncSetAttribute(gemm_bulk<256, 512>,
                         cudaFuncAttributeMaxDynamicSharedMemorySize, SMEM_BN256);
    cudaFuncSetAttribute(gemm_bulk<128, 256>,
                         cudaFuncAttributeMaxDynamicSharedMemorySize, SMEM_BN128);
    cudaFuncSetAttribute(xproj8_kernel,
                         cudaFuncAttributeMaxDynamicSharedMemorySize, XP_SMEM);

    // Pack weights — tile row-count MUST match the consuming GEMM's BN.
    {
        long n1 = (long)kNL * 2 * kDi * kDm / 4;
        long n2 = (long)kNL * kDm * kDi / 4;
        long n3 = (long)kV * kDm / 4;
        pack_w_kernel<256><<<(int)((n1 + 255) / 256), 256>>>(in_proj_w,  wh_in,
                                                             kNL * 2 * kDi, kDm);
        pack_w_kernel<128><<<(int)((n2 + 255) / 256), 256>>>(out_proj_w, wh_out,
                                                             kNL * kDm, kDi);
        pack_w_kernel<256><<<(int)((n3 + 255) / 256), 256>>>(emb,        embh,
                                                             kV, kDm);
    }

    embed_kernel<<<kT, 256>>>(idx, emb);

    for (int l = 0; l < kNL; l++) {
        rmsnorm_kernel<<<kT, 256>>>(x, norm_w + (size_t)l * kDm, xnh);
        gemm_bulk<256, 512><<<dim3(2 * kDi / 256, kT / 128), 512, SMEM_BN256>>>(
            xnh, wh_in + (size_t)l * 2 * kDi * kDm, xz, kT, 2 * kDi, kDm, 0);
        conv_silu8_kernel<<<dim3(kDi / 256, kT / 8), 256>>>(
            conv_w + (size_t)l * kDi * 4, conv_b + (size_t)l * kDi);
        xproj8_kernel<<<kT / 8, 256, XP_SMEM>>>(x_proj_w + (size_t)l * kXP * kDi);
        scan2_kernel<<<kDi / 8, 128>>>(
            A_log + (size_t)l * kDi * kNS,
            dt_proj_w + (size_t)l * kDi,
            dt_proj_b + (size_t)l * kDi,
            D_param + (size_t)l * kDi);
        gemm_bulk<128, 256><<<dim3(kDm / 128, kT / 128), 256, SMEM_BN128>>>(
            ygh, wh_out + (size_t)l * kDm * kDi, x, kT, kDm, kDi, 1);
    }

    rmsnorm_kernel<<<kT, 256>>>(x, norm_f_w, xnh);
    gemm_bulk<256, 512><<<dim3(kV / 256, kT / 128), 512, SMEM_BN256>>>(
        xnh, embh, out, kT, kV, kDm, 0);
}

// round 14
// speedup vs baseline: 2.6643x; 1.0028x over previous
#include <cuda_runtime.h>
#include <cuda_fp16.h>
#include <math.h>
#include <stdint.h>

constexpr int kT  = 2048;
constexpr int kDm = 1024;
constexpr int kDi = 2048;
constexpr int kNL = 4;
constexpr int kNS = 16;
constexpr int kV  = 32000;
constexpr int kXP = 33;

// Packed fp16 buffers. A tiles: 128 rows x 32 halves (8KB), XOR-swizzled.
// B tiles: R rows x 32 halves (R*64 bytes), R=256 for BN=256 GEMMs, 128 else.
__device__ float  g_x  [kT * kDm];
__device__ __align__(16) __half g_xnh[kT * kDm];
__device__ float  g_xz [kT * 2 * kDi];
__device__ float  g_u  [kT * kDi];
__device__ float  g_xp [kT * kXP];
__device__ __align__(16) __half g_ygh[kT * kDi];
__device__ __align__(16) __half g_wh_in [kNL * 2 * kDi * kDm];
__device__ __align__(16) __half g_wh_out[kNL * kDm * kDi];
__device__ __align__(16) __half g_embh  [kV * kDm];

__device__ __forceinline__ uint32_t smem_u32(const void* p) {
    uint32_t a;
    asm("{ .reg .u64 t; cvta.to.shared.u64 t, %1; cvt.u32.u64 %0, t; }"
        : "=r"(a) : "l"(p));
    return a;
}
#define MBAR_INIT(a, n) \
    asm volatile("mbarrier.init.shared.b64 [%0], %1;" :: "r"(a), "r"(n) : "memory")
#define MBAR_EXPECT_TX(a, tx) \
    asm volatile("mbarrier.arrive.expect_tx.shared.b64 _, [%0], %1;" \
                 :: "r"(a), "r"(tx) : "memory")
#define MBAR_WAIT(a, ph) do {                                                \
    asm volatile(                                                            \
        "{\n\t.reg .pred P;\n"                                               \
        "W%=:\n\t"                                                           \
        "mbarrier.try_wait.parity.acquire.cta.shared::cta.b64 P, [%0], %1, 0x989680;\n\t" \
        "@P bra.uni D%=;\n\t"                                                \
        "bra.uni W%=;\n"                                                     \
        "D%=:\n\t}"                                                          \
        :: "r"(a), "r"(ph) : "memory");                                      \
} while (0)
#define BULK_LD(dst, src, bytes, bar) \
    asm volatile("cp.async.bulk.shared::cluster.global.mbarrier::complete_tx::bytes " \
                 "[%0], [%1], %2, [%3];" \
                 :: "r"(dst), "l"(src), "r"(bytes), "r"(bar) : "memory")
#define CP4(dst, src) \
    asm volatile("cp.async.ca.shared.global [%0], [%1], 4;" \
                 :: "r"(dst), "l"(src) : "memory")

// ---------------------------------------------------------------------------
// Weight pack: f32 [N,K] row-major -> fp16 tiles [nb][kb][R x 32], swizzled.
// ---------------------------------------------------------------------------
template <int R>
__global__ void pack_w_kernel(const float* __restrict__ in,
                              __half* __restrict__ out, int N, int K) {
    long i = (long)blockIdx.x * blockDim.x + threadIdx.x;
    long e = i * 4;
    if (e >= (long)N * K) return;
    int n = (int)(e / K), k = (int)(e % K);
    float4 v = *(const float4*)(in + e);
    int nb = n / R, rr = n % R, kb = k >> 5, col = k & 31;
    int NKt = K >> 5;
    size_t off = ((size_t)(nb * NKt + kb) * (R * 64)) +
                 (uint32_t)((rr * 64 + col * 2) ^ ((rr & 7) << 3));
    __half2 h0 = __floats2half2_rn(v.x, v.y);
    __half2 h1 = __floats2half2_rn(v.z, v.w);
    uint2 u;
    u.x = *(uint32_t*)&h0; u.y = *(uint32_t*)&h1;
    *(uint2*)((char*)out + off) = u;
}

__global__ void embed_kernel(const int* __restrict__ idx,
                             const float* __restrict__ emb) {
    int t = blockIdx.x;
    int row = idx[t];
    ((float4*)(g_x + (size_t)t * kDm))[threadIdx.x] =
        ((const float4*)(emb + (size_t)row * kDm))[threadIdx.x];
}

__global__ void rmsnorm_kernel(const float* __restrict__ in,
                               const float* __restrict__ w,
                               __half* __restrict__ out) {
    __shared__ float red[8];
    __shared__ float s_scale;
    int t = blockIdx.x;
    float4 v = ((const float4*)(in + (size_t)t * kDm))[threadIdx.x];
    float ss = v.x * v.x + v.y * v.y + v.z * v.z + v.w * v.w;
    #pragma unroll
    for (int o = 16; o; o >>= 1) ss += __shfl_xor_sync(0xffffffffu, ss, o);
    int warp = threadIdx.x >> 5, lane = threadIdx.x & 31;
    if (lane == 0) red[warp] = ss;
    __syncthreads();
    if (threadIdx.x == 0) {
        float s = 0.f;
        #pragma unroll
        for (int i = 0; i < 8; i++) s += red[i];
        s_scale = rsqrtf(s / (float)kDm + 1e-5f);
    }
    __syncthreads();
    float sc = s_scale;
    float4 wv = ((const float4*)w)[threadIdx.x];
    __half2 h0 = __floats2half2_rn(v.x * sc * wv.x, v.y * sc * wv.y);
    __half2 h1 = __floats2half2_rn(v.z * sc * wv.z, v.w * sc * wv.w);
    int d0 = threadIdx.x * 4;
    int tb = t >> 7, r = t & 127, kb = d0 >> 5, col = d0 & 31;
    size_t off = ((size_t)(tb * (kDm >> 5) + kb) * 8192) +
                 (uint32_t)((r * 64 + col * 2) ^ ((r & 7) << 3));
    uint2 u;
    u.x = *(uint32_t*)&h0; u.y = *(uint32_t*)&h1;
    *(uint2*)((char*)out + off) = u;
}

// ---------------------------------------------------------------------------
// fp16 mma.sync NT GEMM, cp.async.bulk pipeline, S=6 deep.
// ---------------------------------------------------------------------------
template <int BN, int THREADS>
__global__ __launch_bounds__(THREADS, (BN == 128) ? 2 : 1)
void gemm_bulk(const __half* __restrict__ Ap, const __half* __restrict__ Bp,
               float* __restrict__ C, int M, int N, int K, int acc_flag) {
    constexpr int S  = 6;
    constexpr int SB = 8192 + BN * 64;
    constexpr int WNN = BN / 32;
    extern __shared__ char sm[];
    uint32_t sb = smem_u32(sm);

    int tid = threadIdx.x, lane = tid & 31, wrp = tid >> 5;
    int wm = wrp / WNN, wn = wrp % WNN;
    int l2 = lane & 3, l4 = lane >> 2;
    int NKt = K >> 5;

    const char* gA = (const char*)Ap + (size_t)blockIdx.y * NKt * 8192;
    const char* gB = (const char*)Bp + (size_t)blockIdx.x * NKt * (BN * 64);

    if (tid == 0) {
        #pragma unroll
        for (int s = 0; s < S; s++) MBAR_INIT(sb + 8 * s, 1);
    }
    __syncthreads();

    auto issue = [&](int j) {
        uint32_t bar = sb + 8 * (j % S);
        uint32_t dA  = sb + 1024 + (j % S) * SB;
        MBAR_EXPECT_TX(bar, (uint32_t)SB);
        BULK_LD(dA, gA + (size_t)j * 8192, 8192u, bar);
        BULK_LD(dA + 8192, gB + (size_t)j * (BN * 64), (uint32_t)(BN * 64), bar);
    };
    if (tid == 0) {
        #pragma unroll
        for (int j = 0; j < S - 1; j++)
            if (j < NKt) issue(j);
    }

    float acc[4][4][4];
    #pragma unroll
    for (int i = 0; i < 4; i++)
        #pragma unroll
        for (int j = 0; j < 4; j++)
            #pragma unroll
            for (int r = 0; r < 4; r++) acc[i][j][r] = 0.f;

    uint32_t cx[4];
    #pragma unroll
    for (int p = 0; p < 4; p++) cx[p] = (uint32_t)((p * 16 + 4 * l2) ^ (l4 << 3));

    for (int ks = 0; ks < NKt; ks++) {
        MBAR_WAIT(sb + 8 * (ks % S), (ks / S) & 1);

        const char* As = sm + 1024 + (ks % S) * SB;
        const char* Bs = As + 8192;
        #pragma unroll
        for (int ph = 0; ph < 2; ph++) {
            uint32_t af[4][4];
            uint32_t bf[4][2];
            #pragma unroll
            for (int mi = 0; mi < 4; mi++) {
                uint32_t rb = (uint32_t)(wm * 64 + mi * 16 + l4) * 64;
                af[mi][0] = *(const uint32_t*)(As + rb       + cx[ph * 2]);
                af[mi][1] = *(const uint32_t*)(As + rb + 512 + cx[ph * 2]);
                af[mi][2] = *(const uint32_t*)(As + rb       + cx[ph * 2 + 1]);
                af[mi][3] = *(const uint32_t*)(As + rb + 512 + cx[ph * 2 + 1]);
            }
            #pragma unroll
            for (int ni = 0; ni < 4; ni++) {
                uint32_t rb = (uint32_t)(wn * 32 + ni * 8 + l4) * 64;
                bf[ni][0] = *(const uint32_t*)(Bs + rb + cx[ph * 2]);
                bf[ni][1] = *(const uint32_t*)(Bs + rb + cx[ph * 2 + 1]);
            }
            #pragma unroll
            for (int mi = 0; mi < 4; mi++)
                #pragma unroll
                for (int ni = 0; ni < 4; ni++) {
                    asm volatile(
                        "mma.sync.aligned.m16n8k16.row.col.f32.f16.f16.f32 "
                        "{%0,%1,%2,%3}, {%4,%5,%6,%7}, {%8,%9}, {%0,%1,%2,%3};"
                        : "+f"(acc[mi][ni][0]), "+f"(acc[mi][ni][1]),
                          "+f"(acc[mi][ni][2]), "+f"(acc[mi][ni][3])
                        : "r"(af[mi][0]), "r"(af[mi][1]),
                          "r"(af[mi][2]), "r"(af[mi][3]),
                          "r"(bf[ni][0]), "r"(bf[ni][1]));
                }
        }
        __syncthreads();
        if (tid == 0 && ks + S - 1 < NKt) issue(ks + S - 1);
    }

    #pragma unroll
    for (int mi = 0; mi < 4; mi++) {
        int row0 = blockIdx.y * 128 + wm * 64 + mi * 16 + l4;
        #pragma unroll
        for (int ni = 0; ni < 4; ni++) {
            int col0 = blockIdx.x * BN + wn * 32 + ni * 8 + 2 * l2;
            float2* p0 = (float2*)(C + (size_t)row0 * N + col0);
            float2* p1 = (float2*)(C + (size_t)(row0 + 8) * N + col0);
            if (acc_flag) {
                float2 v0 = *p0, v1 = *p1;
                v0.x += acc[mi][ni][0]; v0.y += acc[mi][ni][1];
                v1.x += acc[mi][ni][2]; v1.y += acc[mi][ni][3];
                *p0 = v0; *p1 = v1;
            } else {
                *p0 = make_float2(acc[mi][ni][0], acc[mi][ni][1]);
                *p1 = make_float2(acc[mi][ni][2], acc[mi][ni][3]);
            }
        }
    }
}

constexpr int SMEM_BN256 = 1024 + 6 * (8192 + 256 * 64);   // 148480
constexpr int SMEM_BN128 = 1024 + 6 * (8192 + 128 * 64);   // 99328

// ---------------------------------------------------------------------------
// Causal depthwise conv (K=4) + bias + silu; rolling window, 8 t per thread.
// ---------------------------------------------------------------------------
__global__ void conv_silu8_kernel(const float* __restrict__ cw,
                                  const float* __restrict__ cb) {
    int c  = blockIdx.x * 256 + threadIdx.x;
    int t0 = blockIdx.y * 8;
    const int stride = 2 * kDi;
    float w0 = cw[c * 4 + 0], w1 = cw[c * 4 + 1];
    float w2 = cw[c * 4 + 2], w3 = cw[c * 4 + 3];
    float b  = cb[c];
    float x0 = (t0 >= 3) ? g_xz[(size_t)(t0 - 3) * stride + c] : 0.f;
    float x1 = (t0 >= 2) ? g_xz[(size_t)(t0 - 2) * stride + c] : 0.f;
    float x2 = (t0 >= 1) ? g_xz[(size_t)(t0 - 1) * stride + c] : 0.f;
    #pragma unroll
    for (int i = 0; i < 8; i++) {
        float cur = g_xz[(size_t)(t0 + i) * stride + c];
        float s = b + w0 * x0 + w1 * x1 + w2 * x2 + w3 * cur;
        g_u[(size_t)(t0 + i) * kDi + c] = s / (1.f + __expf(-s));
        x0 = x1; x1 = x2; x2 = cur;
    }
}

// ---------------------------------------------------------------------------
// x_proj, 8 tokens per block: u rows staged in smem, W streamed once/block.
// ---------------------------------------------------------------------------
constexpr int XP_SMEM = 8 * kDi * 4;   // 65536

__global__ __launch_bounds__(256)
void xproj8_kernel(const float* __restrict__ W) {
    extern __shared__ float su[];      // [8][2048]
    int t0 = blockIdx.x * 8;
    const float4* usrc = (const float4*)(g_u + (size_t)t0 * kDi);
    for (int i = threadIdx.x; i < 8 * kDi / 4; i += 256)
        ((float4*)su)[i] = usrc[i];
    __syncthreads();

    int warp = threadIdx.x >> 5, lane = threadIdx.x & 31;
    for (int j = warp; j < kXP; j += 8) {
        const float4* wr = (const float4*)(W + (size_t)j * kDi);
        float acc[8];
        #pragma unroll
        for (int r = 0; r < 8; r++) acc[r] = 0.f;
        #pragma unroll 4
        for (int k = lane; k < kDi / 4; k += 32) {
            float4 bv = wr[k];
            #pragma unroll
            for (int r = 0; r < 8; r++) {
                float4 a = ((const float4*)(su + r * kDi))[k];
                acc[r] += a.x * bv.x + a.y * bv.y + a.z * bv.z + a.w * bv.w;
            }
        }
        #pragma unroll
        for (int r = 0; r < 8; r++) {
            float s = acc[r];
            #pragma unroll
            for (int o = 16; o; o >>= 1) s += __shfl_xor_sync(0xffffffffu, s, o);
            if (lane == 0) g_xp[(t0 + r) * kXP + j] = s;
        }
    }
}

// ---------------------------------------------------------------------------
// Selective scan v2: chunked smem staging + off-path derived precompute.
// ---------------------------------------------------------------------------
__global__ __launch_bounds__(128)
void scan2_kernel(const float* __restrict__ A_log,
                  const float* __restrict__ dtw_,
                  const float* __restrict__ dtb_,
                  const float* __restrict__ Dp_) {
    __shared__ float sxp [2][32][32];
    __shared__ float sraw[2][32];
    __shared__ float su_ [2][32][8];
    __shared__ float sz_ [2][32][8];
    __shared__ float sdt [32][8];
    __shared__ float sdtu[32][8];
    __shared__ float szs [32][8];
    __shared__ float sw2 [32][8];

    int tid = threadIdx.x;
    int d0  = blockIdx.x * 8;
    int n   = tid & 15;
    int dgl = tid >> 4;
    int d   = d0 + dgl;
    float a = -expf(A_log[(size_t)d * kNS + n]);

    int dgd = tid & 7;
    float p_dtw = dtw_[d0 + dgd];
    float p_dtb = dtb_[d0 + dgd];
    float p_Dp  = Dp_[d0 + dgd];

    int kbq = d >> 5, colq = d & 31;

    auto issue = [&](int k) {
        int b = k & 1;
        int t0 = k * 32;
        int i = tid >> 2, j0 = (tid & 3) * 8;
        const float* src = g_xp + (size_t)(t0 + i) * kXP + 1 + j0;
        uint32_t dst = smem_u32(&sxp[b][i][j0]);
        #pragma unroll
        for (int jj = 0; jj < 8; jj++) CP4(dst + 4 * jj, src + jj);
        if (tid < 32)
            CP4(smem_u32(&sraw[b][tid]), g_xp + (size_t)(t0 + tid) * kXP);
        #pragma unroll
        for (int q = 0; q < 2; q++) {
            int e = tid + q * 128;
            int i2 = e >> 3, dg = e & 7;
            CP4(smem_u32(&su_[b][i2][dg]),
                g_u + (size_t)(t0 + i2) * kDi + d0 + dg);
            CP4(smem_u32(&sz_[b][i2][dg]),
                g_xz + (size_t)(t0 + i2) * (2 * kDi) + kDi + d0 + dg);
        }
        asm volatile("cp.async.commit_group;" ::: "memory");
    };

    issue(0);

    float h = 0.f;
    for (int k = 0; k < kT / 32; k++) {
        int b = k & 1;
        asm volatile("cp.async.wait_group 0;" ::: "memory");
        __syncthreads();
        if (k + 1 < kT / 32) issue(k + 1);

        #pragma unroll
        for (int q = 0; q < 2; q++) {
            int e = tid + q * 128;
            int i2 = e >> 3;
            float xv = fmaf(sraw[b][i2], p_dtw, p_dtb);
            float dt = (xv > 20.f) ? xv : log1pf(__expf(xv));
            float u  = su_[b][i2][dgd];
            float z  = sz_[b][i2][dgd];
            float zs = z / (1.f + __expf(-z));
            sdt [i2][dgd] = dt;
            sdtu[i2][dgd] = dt * u;
            szs [i2][dgd] = zs;
            sw2 [i2][dgd] = u * p_Dp * zs;
        }
        __syncthreads();

        int tbase = k * 32;
        #pragma unroll 8
        for (int i = 0; i < 32; i++) {
            float Bn  = sxp[b][i][n];
            float Cn  = sxp[b][i][16 + n];
            float dt  = sdt[i][dgl];
            float dtu = sdtu[i][dgl];
            float dA  = __expf(dt * a);
            h = fmaf(dA, h, dtu * Bn);
            float p = h * Cn;
            p += __shfl_xor_sync(0xffffffffu, p, 8);
            p += __shfl_xor_sync(0xffffffffu, p, 4);
            p += __shfl_xor_sync(0xffffffffu, p, 2);
            p += __shfl_xor_sync(0xffffffffu, p, 1);
            if (n == 0) {
                float y = fmaf(p, szs[i][dgl], sw2[i][dgl]);
                int t = tbase + i;
                int tb = t >> 7, r = t & 127;
                size_t off = ((size_t)(tb * (kDi >> 5) + kbq) * 8192) +
                             (uint32_t)((r * 64 + colq * 2) ^ ((r & 7) << 3));
                *(__half*)((char*)g_ygh + off) = __float2half_rn(y);
            }
        }
    }
}

// ---------------------------------------------------------------------------
extern "C" void kernel_launch(void* const* d_in, const int* in_sizes, int n_in,
                              void* d_out, int out_size) {
    const int*   idx        = (const int*)  d_in[0];
    const float* emb        = (const float*)d_in[1];
    const float* norm_w     = (const float*)d_in[2];
    const float* in_proj_w  = (const float*)d_in[3];
    const float* conv_w     = (const float*)d_in[4];
    const float* conv_b     = (const float*)d_in[5];
    const float* x_proj_w   = (const float*)d_in[6];
    const float* dt_proj_w  = (const float*)d_in[7];
    const float* dt_proj_b  = (const float*)d_in[8];
    const float* A_log      = (const float*)d_in[9];
    const float* D_param    = (const float*)d_in[10];
    const float* out_proj_w = (const float*)d_in[11];
    const float* norm_f_w   = (const float*)d_in[12];
    float* out = (float*)d_out;

    float *x, *xz;
    __half *xnh, *ygh, *wh_in, *wh_out, *embh;
    cudaGetSymbolAddress((void**)&x,      g_x);
    cudaGetSymbolAddress((void**)&xnh,    g_xnh);
    cudaGetSymbolAddress((void**)&xz,     g_xz);
    cudaGetSymbolAddress((void**)&ygh,    g_ygh);
    cudaGetSymbolAddress((void**)&wh_in,  g_wh_in);
    cudaGetSymbolAddress((void**)&wh_out, g_wh_out);
    cudaGetSymbolAddress((void**)&embh,   g_embh);

    cudaFuncSetAttribute(gemm_bulk<256, 512>,
                         cudaFuncAttributeMaxDynamicSharedMemorySize, SMEM_BN256);
    cudaFuncSetAttribute(gemm_bulk<128, 256>,
                         cudaFuncAttributeMaxDynamicSharedMemorySize, SMEM_BN128);
    cudaFuncSetAttribute(xproj8_kernel,
                         cudaFuncAttributeMaxDynamicSharedMemorySize, XP_SMEM);

    long n1 = (long)kNL * 2 * kDi * kDm / 4;
    long n2 = (long)kNL * kDm * kDi / 4;
    long n3 = (long)kV * kDm / 4;

    // Launch order: gemm_bulk<256> in slot 4 for the ncu capture window.
    pack_w_kernel<256><<<(int)((n1 + 255) / 256), 256>>>(in_proj_w,  wh_in,
                                                         kNL * 2 * kDi, kDm);   // 1
    embed_kernel<<<kT, 256>>>(idx, emb);                                        // 2
    rmsnorm_kernel<<<kT, 256>>>(x, norm_w, xnh);                                // 3
    gemm_bulk<256, 512><<<dim3(2 * kDi / 256, kT / 128), 512, SMEM_BN256>>>(    // 4
        xnh, wh_in, xz, kT, 2 * kDi, kDm, 0);
    pack_w_kernel<128><<<(int)((n2 + 255) / 256), 256>>>(out_proj_w, wh_out,
                                                         kNL * kDm, kDi);       // 5
    pack_w_kernel<256><<<(int)((n3 + 255) / 256), 256>>>(emb,        embh,
                                                         kV, kDm);              // 6

    for (int l = 0; l < kNL; l++) {
        if (l > 0) {
            rmsnorm_kernel<<<kT, 256>>>(x, norm_w + (size_t)l * kDm, xnh);
            gemm_bulk<256, 512><<<dim3(2 * kDi / 256, kT / 128), 512, SMEM_BN256>>>(
                xnh, wh_in + (size_t)l * 2 * kDi * kDm, xz, kT, 2 * kDi, kDm, 0);
        }
        conv_silu8_kernel<<<dim3(kDi / 256, kT / 8), 256>>>(
            conv_w + (size_t)l * kDi * 4, conv_b + (size_t)l * kDi);
        xproj8_kernel<<<kT / 8, 256, XP_SMEM>>>(x_proj_w + (size_t)l * kXP * kDi);
        scan2_kernel<<<kDi / 8, 128>>>(
            A_log + (size_t)l * kDi * kNS,
            dt_proj_w + (size_t)l * kDi,
            dt_proj_b + (size_t)l * kDi,
            D_param + (size_t)l * kDi);
        gemm_bulk<128, 256><<<dim3(kDm / 128, kT / 128), 256, SMEM_BN128>>>(
            ygh, wh_out + (size_t)l * kDm * kDi, x, kT, kDm, kDi, 1);
    }

    rmsnorm_kernel<<<kT, 256>>>(x, norm_f_w, xnh);
    gemm_bulk<256, 512><<<dim3(kV / 256, kT / 128), 512, SMEM_BN256>>>(
        xnh, embh, out, kT, kV, kDm, 0);
}

// round 15
// speedup vs baseline: 4.4376x; 1.6655x over previous
#include <cuda_runtime.h>
#include <cuda_fp16.h>
#include <math.h>
#include <stdint.h>

constexpr int kT  = 2048;
constexpr int kDm = 1024;
constexpr int kDi = 2048;
constexpr int kNL = 4;
constexpr int kNS = 16;
constexpr int kV  = 32000;
constexpr int kXP = 33;

// Packed fp16 buffers. A tiles: 128 rows x 32 halves (8KB), XOR-swizzled.
// B tiles: R rows x 32 halves (R*64 bytes), R=256 for BN=256 GEMMs, 128 else.
__device__ float  g_x  [kT * kDm];
__device__ __align__(16) __half g_xnh[kT * kDm];
__device__ float  g_xz [kT * 2 * kDi];
__device__ float  g_u  [kT * kDi];
__device__ float  g_xp [kT * kXP];
__device__ __align__(16) __half g_ygh[kT * kDi];
__device__ __align__(16) __half g_wh_in [kNL * 2 * kDi * kDm];
__device__ __align__(16) __half g_wh_out[kNL * kDm * kDi];
__device__ __align__(16) __half g_embh  [kV * kDm];

__device__ __forceinline__ uint32_t smem_u32(const void* p) {
    uint32_t a;
    asm("{ .reg .u64 t; cvta.to.shared.u64 t, %1; cvt.u32.u64 %0, t; }"
        : "=r"(a) : "l"(p));
    return a;
}
#define MBAR_INIT(a, n) \
    asm volatile("mbarrier.init.shared.b64 [%0], %1;" :: "r"(a), "r"(n) : "memory")
#define MBAR_EXPECT_TX(a, tx) \
    asm volatile("mbarrier.arrive.expect_tx.shared.b64 _, [%0], %1;" \
                 :: "r"(a), "r"(tx) : "memory")
#define MBAR_WAIT(a, ph) do {                                                \
    asm volatile(                                                            \
        "{\n\t.reg .pred P;\n"                                               \
        "W%=:\n\t"                                                           \
        "mbarrier.try_wait.parity.acquire.cta.shared::cta.b64 P, [%0], %1, 0x989680;\n\t" \
        "@P bra.uni D%=;\n\t"                                                \
        "bra.uni W%=;\n"                                                     \
        "D%=:\n\t}"                                                          \
        :: "r"(a), "r"(ph) : "memory");                                      \
} while (0)
#define BULK_LD(dst, src, bytes, bar) \
    asm volatile("cp.async.bulk.shared::cluster.global.mbarrier::complete_tx::bytes " \
                 "[%0], [%1], %2, [%3];" \
                 :: "r"(dst), "l"(src), "r"(bytes), "r"(bar) : "memory")
#define CP4(dst, src) \
    asm volatile("cp.async.ca.shared.global [%0], [%1], 4;" \
                 :: "r"(dst), "l"(src) : "memory")

// ---------------------------------------------------------------------------
// Weight pack: f32 [N,K] row-major -> fp16 tiles [nb][kb][R x 32], swizzled.
// ---------------------------------------------------------------------------
template <int R>
__global__ void pack_w_kernel(const float* __restrict__ in,
                              __half* __restrict__ out, int N, int K) {
    long i = (long)blockIdx.x * blockDim.x + threadIdx.x;
    long e = i * 4;
    if (e >= (long)N * K) return;
    int n = (int)(e / K), k = (int)(e % K);
    float4 v = *(const float4*)(in + e);
    int nb = n / R, rr = n % R, kb = k >> 5, col = k & 31;
    int NKt = K >> 5;
    size_t off = ((size_t)(nb * NKt + kb) * (R * 64)) +
                 (uint32_t)((rr * 64 + col * 2) ^ ((rr & 7) << 3));
    __half2 h0 = __floats2half2_rn(v.x, v.y);
    __half2 h1 = __floats2half2_rn(v.z, v.w);
    uint2 u;
    u.x = *(uint32_t*)&h0; u.y = *(uint32_t*)&h1;
    *(uint2*)((char*)out + off) = u;
}

__global__ void embed_kernel(const int* __restrict__ idx,
                             const float* __restrict__ emb) {
    int t = blockIdx.x;
    int row = idx[t];
    ((float4*)(g_x + (size_t)t * kDm))[threadIdx.x] =
        ((const float4*)(emb + (size_t)row * kDm))[threadIdx.x];
}

__global__ void rmsnorm_kernel(const float* __restrict__ in,
                               const float* __restrict__ w,
                               __half* __restrict__ out) {
    __shared__ float red[8];
    __shared__ float s_scale;
    int t = blockIdx.x;
    float4 v = ((const float4*)(in + (size_t)t * kDm))[threadIdx.x];
    float ss = v.x * v.x + v.y * v.y + v.z * v.z + v.w * v.w;
    #pragma unroll
    for (int o = 16; o; o >>= 1) ss += __shfl_xor_sync(0xffffffffu, ss, o);
    int warp = threadIdx.x >> 5, lane = threadIdx.x & 31;
    if (lane == 0) red[warp] = ss;
    __syncthreads();
    if (threadIdx.x == 0) {
        float s = 0.f;
        #pragma unroll
        for (int i = 0; i < 8; i++) s += red[i];
        s_scale = rsqrtf(s / (float)kDm + 1e-5f);
    }
    __syncthreads();
    float sc = s_scale;
    float4 wv = ((const float4*)w)[threadIdx.x];
    __half2 h0 = __floats2half2_rn(v.x * sc * wv.x, v.y * sc * wv.y);
    __half2 h1 = __floats2half2_rn(v.z * sc * wv.z, v.w * sc * wv.w);
    int d0 = threadIdx.x * 4;
    int tb = t >> 7, r = t & 127, kb = d0 >> 5, col = d0 & 31;
    size_t off = ((size_t)(tb * (kDm >> 5) + kb) * 8192) +
                 (uint32_t)((r * 64 + col * 2) ^ ((r & 7) << 3));
    uint2 u;
    u.x = *(uint32_t*)&h0; u.y = *(uint32_t*)&h1;
    *(uint2*)((char*)out + off) = u;
}

// ---------------------------------------------------------------------------
// fp16 mma.sync NT GEMM, cp.async.bulk pipeline, S=6 (R14, best known).
// ---------------------------------------------------------------------------
template <int BN, int THREADS>
__global__ __launch_bounds__(THREADS, (BN == 128) ? 2 : 1)
void gemm_bulk(const __half* __restrict__ Ap, const __half* __restrict__ Bp,
               float* __restrict__ C, int M, int N, int K, int acc_flag) {
    constexpr int S  = 6;
    constexpr int SB = 8192 + BN * 64;
    constexpr int WNN = BN / 32;
    extern __shared__ char sm[];
    uint32_t sb = smem_u32(sm);

    int tid = threadIdx.x, lane = tid & 31, wrp = tid >> 5;
    int wm = wrp / WNN, wn = wrp % WNN;
    int l2 = lane & 3, l4 = lane >> 2;
    int NKt = K >> 5;

    const char* gA = (const char*)Ap + (size_t)blockIdx.y * NKt * 8192;
    const char* gB = (const char*)Bp + (size_t)blockIdx.x * NKt * (BN * 64);

    if (tid == 0) {
        #pragma unroll
        for (int s = 0; s < S; s++) MBAR_INIT(sb + 8 * s, 1);
    }
    __syncthreads();

    auto issue = [&](int j) {
        uint32_t bar = sb + 8 * (j % S);
        uint32_t dA  = sb + 1024 + (j % S) * SB;
        MBAR_EXPECT_TX(bar, (uint32_t)SB);
        BULK_LD(dA, gA + (size_t)j * 8192, 8192u, bar);
        BULK_LD(dA + 8192, gB + (size_t)j * (BN * 64), (uint32_t)(BN * 64), bar);
    };
    if (tid == 0) {
        #pragma unroll
        for (int j = 0; j < S - 1; j++)
            if (j < NKt) issue(j);
    }

    float acc[4][4][4];
    #pragma unroll
    for (int i = 0; i < 4; i++)
        #pragma unroll
        for (int j = 0; j < 4; j++)
            #pragma unroll
            for (int r = 0; r < 4; r++) acc[i][j][r] = 0.f;

    uint32_t cx[4];
    #pragma unroll
    for (int p = 0; p < 4; p++) cx[p] = (uint32_t)((p * 16 + 4 * l2) ^ (l4 << 3));

    for (int ks = 0; ks < NKt; ks++) {
        MBAR_WAIT(sb + 8 * (ks % S), (ks / S) & 1);

        const char* As = sm + 1024 + (ks % S) * SB;
        const char* Bs = As + 8192;
        #pragma unroll
        for (int ph = 0; ph < 2; ph++) {
            uint32_t af[4][4];
            uint32_t bf[4][2];
            #pragma unroll
            for (int mi = 0; mi < 4; mi++) {
                uint32_t rb = (uint32_t)(wm * 64 + mi * 16 + l4) * 64;
                af[mi][0] = *(const uint32_t*)(As + rb       + cx[ph * 2]);
                af[mi][1] = *(const uint32_t*)(As + rb + 512 + cx[ph * 2]);
                af[mi][2] = *(const uint32_t*)(As + rb       + cx[ph * 2 + 1]);
                af[mi][3] = *(const uint32_t*)(As + rb + 512 + cx[ph * 2 + 1]);
            }
            #pragma unroll
            for (int ni = 0; ni < 4; ni++) {
                uint32_t rb = (uint32_t)(wn * 32 + ni * 8 + l4) * 64;
                bf[ni][0] = *(const uint32_t*)(Bs + rb + cx[ph * 2]);
                bf[ni][1] = *(const uint32_t*)(Bs + rb + cx[ph * 2 + 1]);
            }
            #pragma unroll
            for (int mi = 0; mi < 4; mi++)
                #pragma unroll
                for (int ni = 0; ni < 4; ni++) {
                    asm volatile(
                        "mma.sync.aligned.m16n8k16.row.col.f32.f16.f16.f32 "
                        "{%0,%1,%2,%3}, {%4,%5,%6,%7}, {%8,%9}, {%0,%1,%2,%3};"
                        : "+f"(acc[mi][ni][0]), "+f"(acc[mi][ni][1]),
                          "+f"(acc[mi][ni][2]), "+f"(acc[mi][ni][3])
                        : "r"(af[mi][0]), "r"(af[mi][1]),
                          "r"(af[mi][2]), "r"(af[mi][3]),
                          "r"(bf[ni][0]), "r"(bf[ni][1]));
                }
        }
        __syncthreads();
        if (tid == 0 && ks + S - 1 < NKt) issue(ks + S - 1);
    }

    #pragma unroll
    for (int mi = 0; mi < 4; mi++) {
        int row0 = blockIdx.y * 128 + wm * 64 + mi * 16 + l4;
        #pragma unroll
        for (int ni = 0; ni < 4; ni++) {
            int col0 = blockIdx.x * BN + wn * 32 + ni * 8 + 2 * l2;
            float2* p0 = (float2*)(C + (size_t)row0 * N + col0);
            float2* p1 = (float2*)(C + (size_t)(row0 + 8) * N + col0);
            if (acc_flag) {
                float2 v0 = *p0, v1 = *p1;
                v0.x += acc[mi][ni][0]; v0.y += acc[mi][ni][1];
                v1.x += acc[mi][ni][2]; v1.y += acc[mi][ni][3];
                *p0 = v0; *p1 = v1;
            } else {
                *p0 = make_float2(acc[mi][ni][0], acc[mi][ni][1]);
                *p1 = make_float2(acc[mi][ni][2], acc[mi][ni][3]);
            }
        }
    }
}

constexpr int SMEM_BN256 = 1024 + 6 * (8192 + 256 * 64);   // 148480
constexpr int SMEM_BN128 = 1024 + 6 * (8192 + 128 * 64);   // 99328

// ---------------------------------------------------------------------------
// Causal depthwise conv (K=4) + bias + silu; rolling window, 8 t per thread.
// ---------------------------------------------------------------------------
__global__ void conv_silu8_kernel(const float* __restrict__ cw,
                                  const float* __restrict__ cb) {
    int c  = blockIdx.x * 256 + threadIdx.x;
    int t0 = blockIdx.y * 8;
    const int stride = 2 * kDi;
    float w0 = cw[c * 4 + 0], w1 = cw[c * 4 + 1];
    float w2 = cw[c * 4 + 2], w3 = cw[c * 4 + 3];
    float b  = cb[c];
    float x0 = (t0 >= 3) ? g_xz[(size_t)(t0 - 3) * stride + c] : 0.f;
    float x1 = (t0 >= 2) ? g_xz[(size_t)(t0 - 2) * stride + c] : 0.f;
    float x2 = (t0 >= 1) ? g_xz[(size_t)(t0 - 1) * stride + c] : 0.f;
    #pragma unroll
    for (int i = 0; i < 8; i++) {
        float cur = g_xz[(size_t)(t0 + i) * stride + c];
        float s = b + w0 * x0 + w1 * x1 + w2 * x2 + w3 * cur;
        g_u[(size_t)(t0 + i) * kDi + c] = s / (1.f + __expf(-s));
        x0 = x1; x1 = x2; x2 = cur;
    }
}

// ---------------------------------------------------------------------------
// x_proj, 8 tokens per block: u rows staged in smem, W streamed once/block.
// ---------------------------------------------------------------------------
constexpr int XP_SMEM = 8 * kDi * 4;   // 65536

__global__ __launch_bounds__(256)
void xproj8_kernel(const float* __restrict__ W) {
    extern __shared__ float su[];      // [8][2048]
    int t0 = blockIdx.x * 8;
    const float4* usrc = (const float4*)(g_u + (size_t)t0 * kDi);
    for (int i = threadIdx.x; i < 8 * kDi / 4; i += 256)
        ((float4*)su)[i] = usrc[i];
    __syncthreads();

    int warp = threadIdx.x >> 5, lane = threadIdx.x & 31;
    for (int j = warp; j < kXP; j += 8) {
        const float4* wr = (const float4*)(W + (size_t)j * kDi);
        float acc[8];
        #pragma unroll
        for (int r = 0; r < 8; r++) acc[r] = 0.f;
        #pragma unroll 4
        for (int k = lane; k < kDi / 4; k += 32) {
            float4 bv = wr[k];
            #pragma unroll
            for (int r = 0; r < 8; r++) {
                float4 a = ((const float4*)(su + r * kDi))[k];
                acc[r] += a.x * bv.x + a.y * bv.y + a.z * bv.z + a.w * bv.w;
            }
        }
        #pragma unroll
        for (int r = 0; r < 8; r++) {
            float s = acc[r];
            #pragma unroll
            for (int o = 16; o; o >>= 1) s += __shfl_xor_sync(0xffffffffu, s, o);
            if (lane == 0) g_xp[(t0 + r) * kXP + j] = s;
        }
    }
}

// ---------------------------------------------------------------------------
// Selective scan v3: per-chunk precompute of dA/db into REGISTERS; the serial
// recurrence is a single FMA chain; cross-lane reduce batched via smem.
// Block = 128 threads = 8 channels x 16 states. Grid = kDi/8 = 256.
// ---------------------------------------------------------------------------
__global__ __launch_bounds__(128)
void scan3_kernel(const float* __restrict__ A_log,
                  const float* __restrict__ dtw_,
                  const float* __restrict__ dtb_,
                  const float* __restrict__ Dp_) {
    __shared__ float sxp [2][32][32];   // [i][0..15]=B, [16..31]=C
    __shared__ float sraw[2][32];       // xp[t][0]
    __shared__ float su_ [2][32][8];
    __shared__ float sz_ [2][32][8];
    __shared__ float sdt [32][8];
    __shared__ float sdtu[32][8];
    __shared__ float szs [32][8];
    __shared__ float sw2 [32][8];
    __shared__ float sp  [32][8][16];   // h*C per (t, d, n)

    int tid = threadIdx.x;
    int d0  = blockIdx.x * 8;
    int n   = tid & 15;        // state index
    int dgl = tid >> 4;        // channel group 0..7
    int d   = d0 + dgl;
    float a = -expf(A_log[(size_t)d * kNS + n]);

    int dgd = tid & 7;
    float p_dtw = dtw_[d0 + dgd];
    float p_dtb = dtb_[d0 + dgd];
    float p_Dp  = Dp_[d0 + dgd];

    int r0 = (tid + (tid >> 4)) & 15;   // rotation for conflict-free reduce

    auto issue = [&](int k) {
        int b = k & 1;
        int t0 = k * 32;
        int i = tid >> 2, j0 = (tid & 3) * 8;
        const float* src = g_xp + (size_t)(t0 + i) * kXP + 1 + j0;
        uint32_t dst = smem_u32(&sxp[b][i][j0]);
        #pragma unroll
        for (int jj = 0; jj < 8; jj++) CP4(dst + 4 * jj, src + jj);
        if (tid < 32)
            CP4(smem_u32(&sraw[b][tid]), g_xp + (size_t)(t0 + tid) * kXP);
        #pragma unroll
        for (int q = 0; q < 2; q++) {
            int e = tid + q * 128;
            int i2 = e >> 3, dg = e & 7;
            CP4(smem_u32(&su_[b][i2][dg]),
                g_u + (size_t)(t0 + i2) * kDi + d0 + dg);
            CP4(smem_u32(&sz_[b][i2][dg]),
                g_xz + (size_t)(t0 + i2) * (2 * kDi) + kDi + d0 + dg);
        }
        asm volatile("cp.async.commit_group;" ::: "memory");
    };

    issue(0);

    float h = 0.f;
    for (int k = 0; k < kT / 32; k++) {
        int b = k & 1;
        asm volatile("cp.async.wait_group 0;" ::: "memory");
        __syncthreads();
        if (k + 1 < kT / 32) issue(k + 1);

        // derive1: dt, dt*u, silu(z), u*Dp*silu(z)   (2 elements per thread)
        #pragma unroll
        for (int q = 0; q < 2; q++) {
            int e = tid + q * 128;
            int i2 = e >> 3;
            float xv = fmaf(sraw[b][i2], p_dtw, p_dtb);
            float dt = (xv > 20.f) ? xv : log1pf(__expf(xv));
            float u  = su_[b][i2][dgd];
            float z  = sz_[b][i2][dgd];
            float zs = z / (1.f + __expf(-z));
            sdt [i2][dgd] = dt;
            sdtu[i2][dgd] = dt * u;
            szs [i2][dgd] = zs;
            sw2 [i2][dgd] = u * p_Dp * zs;
        }
        __syncthreads();

        // derive2 (registers): dA_i, db_i, C_i for this thread's (d, n)
        float rdA[32], rdb[32], rC[32];
        #pragma unroll
        for (int i = 0; i < 32; i++) {
            rdA[i] = __expf(sdt[i][dgl] * a);
            rdb[i] = sdtu[i][dgl] * sxp[b][i][n];
            rC[i]  = sxp[b][i][16 + n];
        }

        // serial recurrence: pure FMA chain; p stored for batched reduce
        #pragma unroll
        for (int i = 0; i < 32; i++) {
            h = fmaf(rdA[i], h, rdb[i]);
            sp[i][dgl][n] = h * rC[i];
        }
        __syncthreads();

        // batched reduce + gate + packed fp16 store (2 outputs per thread)
        int tbase = k * 32;
        #pragma unroll
        for (int q = 0; q < 2; q++) {
            int e = tid + q * 128;
            int i = e >> 3, dg = e & 7;
            float s = 0.f;
            #pragma unroll
            for (int kk = 0; kk < 16; kk++)
                s += sp[i][dg][(r0 + kk) & 15];
            float y = fmaf(s, szs[i][dg], sw2[i][dg]);
            int t = tbase + i;
            int dd = d0 + dg;
            int kbq = dd >> 5, colq = dd & 31;
            int tb = t >> 7, r = t & 127;
            size_t off = ((size_t)(tb * (kDi >> 5) + kbq) * 8192) +
                         (uint32_t)((r * 64 + colq * 2) ^ ((r & 7) << 3));
            *(__half*)((char*)g_ygh + off) = __float2half_rn(y);
        }
        __syncthreads();
    }
}

// ---------------------------------------------------------------------------
extern "C" void kernel_launch(void* const* d_in, const int* in_sizes, int n_in,
                              void* d_out, int out_size) {
    const int*   idx        = (const int*)  d_in[0];
    const float* emb        = (const float*)d_in[1];
    const float* norm_w     = (const float*)d_in[2];
    const float* in_proj_w  = (const float*)d_in[3];
    const float* conv_w     = (const float*)d_in[4];
    const float* conv_b     = (const float*)d_in[5];
    const float* x_proj_w   = (const float*)d_in[6];
    const float* dt_proj_w  = (const float*)d_in[7];
    const float* dt_proj_b  = (const float*)d_in[8];
    const float* A_log      = (const float*)d_in[9];
    const float* D_param    = (const float*)d_in[10];
    const float* out_proj_w = (const float*)d_in[11];
    const float* norm_f_w   = (const float*)d_in[12];
    float* out = (float*)d_out;

    float *x, *xz;
    __half *xnh, *ygh, *wh_in, *wh_out, *embh;
    cudaGetSymbolAddress((void**)&x,      g_x);
    cudaGetSymbolAddress((void**)&xnh,    g_xnh);
    cudaGetSymbolAddress((void**)&xz,     g_xz);
    cudaGetSymbolAddress((void**)&ygh,    g_ygh);
    cudaGetSymbolAddress((void**)&wh_in,  g_wh_in);
    cudaGetSymbolAddress((void**)&wh_out, g_wh_out);
    cudaGetSymbolAddress((void**)&embh,   g_embh);

    cudaFuncSetAttribute(gemm_bulk<256, 512>,
                         cudaFuncAttributeMaxDynamicSharedMemorySize, SMEM_BN256);
    cudaFuncSetAttribute(gemm_bulk<128, 256>,
                         cudaFuncAttributeMaxDynamicSharedMemorySize, SMEM_BN128);
    cudaFuncSetAttribute(xproj8_kernel,
                         cudaFuncAttributeMaxDynamicSharedMemorySize, XP_SMEM);

    long n1 = (long)kNL * 2 * kDi * kDm / 4;
    long n2 = (long)kNL * kDm * kDi / 4;
    long n3 = (long)kV * kDm / 4;

    // Launch order: gemm_bulk<256> in slot 4 for the ncu capture window.
    pack_w_kernel<256><<<(int)((n1 + 255) / 256), 256>>>(in_proj_w,  wh_in,
                                                         kNL * 2 * kDi, kDm);   // 1
    embed_kernel<<<kT, 256>>>(idx, emb);                                        // 2
    rmsnorm_kernel<<<kT, 256>>>(x, norm_w, xnh);                                // 3
    gemm_bulk<256, 512><<<dim3(2 * kDi / 256, kT / 128), 512, SMEM_BN256>>>(    // 4
        xnh, wh_in, xz, kT, 2 * kDi, kDm, 0);
    pack_w_kernel<128><<<(int)((n2 + 255) / 256), 256>>>(out_proj_w, wh_out,
                                                         kNL * kDm, kDi);       // 5
    pack_w_kernel<256><<<(int)((n3 + 255) / 256), 256>>>(emb,        embh,
                                                         kV, kDm);              // 6

    for (int l = 0; l < kNL; l++) {
        if (l > 0) {
            rmsnorm_kernel<<<kT, 256>>>(x, norm_w + (size_t)l * kDm, xnh);
            gemm_bulk<256, 512><<<dim3(2 * kDi / 256, kT / 128), 512, SMEM_BN256>>>(
                xnh, wh_in + (size_t)l * 2 * kDi * kDm, xz, kT, 2 * kDi, kDm, 0);
        }
        conv_silu8_kernel<<<dim3(kDi / 256, kT / 8), 256>>>(
            conv_w + (size_t)l * kDi * 4, conv_b + (size_t)l * kDi);
        xproj8_kernel<<<kT / 8, 256, XP_SMEM>>>(x_proj_w + (size_t)l * kXP * kDi);
        scan3_kernel<<<kDi / 8, 128>>>(
            A_log + (size_t)l * kDi * kNS,
            dt_proj_w + (size_t)l * kDi,
            dt_proj_b + (size_t)l * kDi,
            D_param + (size_t)l * kDi);
        gemm_bulk<128, 256><<<dim3(kDm / 128, kT / 128), 256, SMEM_BN128>>>(
            ygh, wh_out + (size_t)l * kDm * kDi, x, kT, kDm, kDi, 1);
    }

    rmsnorm_kernel<<<kT, 256>>>(x, norm_f_w, xnh);
    gemm_bulk<256, 512><<<dim3(kV / 256, kT / 128), 512, SMEM_BN256>>>(
        xnh, embh, out, kT, kV, kDm, 0);
}

// round 16
// speedup vs baseline: 4.7475x; 1.0699x over previous
#include <cuda_runtime.h>
#include <cuda_fp16.h>
#include <math.h>
#include <stdint.h>

constexpr int kT  = 2048;
constexpr int kDm = 1024;
constexpr int kDi = 2048;
constexpr int kNL = 4;
constexpr int kNS = 16;
constexpr int kV  = 32000;
constexpr int kXP = 33;

// Packed fp16 buffers. A tiles: 128 rows x 32 halves (8KB), XOR-swizzled.
// B tiles: R rows x 32 halves (R*64 bytes), R=256 for BN=256 GEMMs, 128 else.
__device__ float  g_x  [kT * kDm];
__device__ __align__(16) __half g_xnh[kT * kDm];
__device__ float  g_xz [kT * 2 * kDi];
__device__ float  g_u  [kT * kDi];
__device__ float  g_xp [kT * kXP];
__device__ __align__(16) __half g_ygh[kT * kDi];
__device__ __align__(16) __half g_wh_in [kNL * 2 * kDi * kDm];
__device__ __align__(16) __half g_wh_out[kNL * kDm * kDi];
__device__ __align__(16) __half g_embh  [kV * kDm];

__device__ __forceinline__ uint32_t smem_u32(const void* p) {
    uint32_t a;
    asm("{ .reg .u64 t; cvta.to.shared.u64 t, %1; cvt.u32.u64 %0, t; }"
        : "=r"(a) : "l"(p));
    return a;
}
#define MBAR_INIT(a, n) \
    asm volatile("mbarrier.init.shared.b64 [%0], %1;" :: "r"(a), "r"(n) : "memory")
#define MBAR_EXPECT_TX(a, tx) \
    asm volatile("mbarrier.arrive.expect_tx.shared.b64 _, [%0], %1;" \
                 :: "r"(a), "r"(tx) : "memory")
#define MBAR_ARRIVE(a) \
    asm volatile("mbarrier.arrive.shared.b64 _, [%0];" :: "r"(a) : "memory")
#define MBAR_WAIT(a, ph) do {                                                \
    asm volatile(                                                            \
        "{\n\t.reg .pred P;\n"                                               \
        "W%=:\n\t"                                                           \
        "mbarrier.try_wait.parity.acquire.cta.shared::cta.b64 P, [%0], %1, 0x989680;\n\t" \
        "@P bra.uni D%=;\n\t"                                                \
        "bra.uni W%=;\n"                                                     \
        "D%=:\n\t}"                                                          \
        :: "r"(a), "r"(ph) : "memory");                                      \
} while (0)
#define BULK_LD(dst, src, bytes, bar) \
    asm volatile("cp.async.bulk.shared::cluster.global.mbarrier::complete_tx::bytes " \
                 "[%0], [%1], %2, [%3];" \
                 :: "r"(dst), "l"(src), "r"(bytes), "r"(bar) : "memory")
#define CP4(dst, src) \
    asm volatile("cp.async.ca.shared.global [%0], [%1], 4;" \
                 :: "r"(dst), "l"(src) : "memory")

// ---------------------------------------------------------------------------
// Weight pack: f32 [N,K] row-major -> fp16 tiles [nb][kb][R x 32], swizzled.
// ---------------------------------------------------------------------------
template <int R>
__global__ void pack_w_kernel(const float* __restrict__ in,
                              __half* __restrict__ out, int N, int K) {
    long i = (long)blockIdx.x * blockDim.x + threadIdx.x;
    long e = i * 4;
    if (e >= (long)N * K) return;
    int n = (int)(e / K), k = (int)(e % K);
    float4 v = *(const float4*)(in + e);
    int nb = n / R, rr = n % R, kb = k >> 5, col = k & 31;
    int NKt = K >> 5;
    size_t off = ((size_t)(nb * NKt + kb) * (R * 64)) +
                 (uint32_t)((rr * 64 + col * 2) ^ ((rr & 7) << 3));
    __half2 h0 = __floats2half2_rn(v.x, v.y);
    __half2 h1 = __floats2half2_rn(v.z, v.w);
    uint2 u;
    u.x = *(uint32_t*)&h0; u.y = *(uint32_t*)&h1;
    *(uint2*)((char*)out + off) = u;
}

__global__ void embed_kernel(const int* __restrict__ idx,
                             const float* __restrict__ emb) {
    int t = blockIdx.x;
    int row = idx[t];
    ((float4*)(g_x + (size_t)t * kDm))[threadIdx.x] =
        ((const float4*)(emb + (size_t)row * kDm))[threadIdx.x];
}

__global__ void rmsnorm_kernel(const float* __restrict__ in,
                               const float* __restrict__ w,
                               __half* __restrict__ out) {
    __shared__ float red[8];
    __shared__ float s_scale;
    int t = blockIdx.x;
    float4 v = ((const float4*)(in + (size_t)t * kDm))[threadIdx.x];
    float ss = v.x * v.x + v.y * v.y + v.z * v.z + v.w * v.w;
    #pragma unroll
    for (int o = 16; o; o >>= 1) ss += __shfl_xor_sync(0xffffffffu, ss, o);
    int warp = threadIdx.x >> 5, lane = threadIdx.x & 31;
    if (lane == 0) red[warp] = ss;
    __syncthreads();
    if (threadIdx.x == 0) {
        float s = 0.f;
        #pragma unroll
        for (int i = 0; i < 8; i++) s += red[i];
        s_scale = rsqrtf(s / (float)kDm + 1e-5f);
    }
    __syncthreads();
    float sc = s_scale;
    float4 wv = ((const float4*)w)[threadIdx.x];
    __half2 h0 = __floats2half2_rn(v.x * sc * wv.x, v.y * sc * wv.y);
    __half2 h1 = __floats2half2_rn(v.z * sc * wv.z, v.w * sc * wv.w);
    int d0 = threadIdx.x * 4;
    int tb = t >> 7, r = t & 127, kb = d0 >> 5, col = d0 & 31;
    size_t off = ((size_t)(tb * (kDm >> 5) + kb) * 8192) +
                 (uint32_t)((r * 64 + col * 2) ^ ((r & 7) << 3));
    uint2 u;
    u.x = *(uint32_t*)&h0; u.y = *(uint32_t*)&h1;
    *(uint2*)((char*)out + off) = u;
}

// ---------------------------------------------------------------------------
// fp16 mma.sync NT GEMM, cp.async.bulk pipeline, S=6, producer/consumer
// empty-barrier ring instead of per-stage __syncthreads (warps decouple).
// smem layout: [0, 8*S): full mbarriers; [8*S, 16*S): empty mbarriers;
//              data at 1024.
// ---------------------------------------------------------------------------
template <int BN, int THREADS>
__global__ __launch_bounds__(THREADS, (BN == 128) ? 2 : 1)
void gemm_bulk(const __half* __restrict__ Ap, const __half* __restrict__ Bp,
               float* __restrict__ C, int M, int N, int K, int acc_flag) {
    constexpr int S  = 6;
    constexpr int SB = 8192 + BN * 64;
    constexpr int WNN = BN / 32;
    constexpr int NW  = THREADS / 32;
    extern __shared__ char sm[];
    uint32_t sb = smem_u32(sm);

    int tid = threadIdx.x, lane = tid & 31, wrp = tid >> 5;
    int wm = wrp / WNN, wn = wrp % WNN;
    int l2 = lane & 3, l4 = lane >> 2;
    int NKt = K >> 5;

    const char* gA = (const char*)Ap + (size_t)blockIdx.y * NKt * 8192;
    const char* gB = (const char*)Bp + (size_t)blockIdx.x * NKt * (BN * 64);

    if (tid == 0) {
        #pragma unroll
        for (int s = 0; s < S; s++) {
            MBAR_INIT(sb + 8 * s, 1);                 // full
            MBAR_INIT(sb + 8 * (S + s), NW);          // empty (1 arrive/warp)
        }
    }
    __syncthreads();

    auto issue = [&](int j) {
        uint32_t bar = sb + 8 * (j % S);
        uint32_t dA  = sb + 1024 + (j % S) * SB;
        MBAR_EXPECT_TX(bar, (uint32_t)SB);
        BULK_LD(dA, gA + (size_t)j * 8192, 8192u, bar);
        BULK_LD(dA + 8192, gB + (size_t)j * (BN * 64), (uint32_t)(BN * 64), bar);
    };
    if (tid == 0) {
        #pragma unroll
        for (int j = 0; j < S - 1; j++)
            if (j < NKt) issue(j);
    }

    float acc[4][4][4];
    #pragma unroll
    for (int i = 0; i < 4; i++)
        #pragma unroll
        for (int j = 0; j < 4; j++)
            #pragma unroll
            for (int r = 0; r < 4; r++) acc[i][j][r] = 0.f;

    uint32_t cx[4];
    #pragma unroll
    for (int p = 0; p < 4; p++) cx[p] = (uint32_t)((p * 16 + 4 * l2) ^ (l4 << 3));

    for (int ks = 0; ks < NKt; ks++) {
        MBAR_WAIT(sb + 8 * (ks % S), (ks / S) & 1);

        const char* As = sm + 1024 + (ks % S) * SB;
        const char* Bs = As + 8192;
        #pragma unroll
        for (int ph = 0; ph < 2; ph++) {
            uint32_t af[4][4];
            uint32_t bf[4][2];
            #pragma unroll
            for (int mi = 0; mi < 4; mi++) {
                uint32_t rb = (uint32_t)(wm * 64 + mi * 16 + l4) * 64;
                af[mi][0] = *(const uint32_t*)(As + rb       + cx[ph * 2]);
                af[mi][1] = *(const uint32_t*)(As + rb + 512 + cx[ph * 2]);
                af[mi][2] = *(const uint32_t*)(As + rb       + cx[ph * 2 + 1]);
                af[mi][3] = *(const uint32_t*)(As + rb + 512 + cx[ph * 2 + 1]);
            }
            #pragma unroll
            for (int ni = 0; ni < 4; ni++) {
                uint32_t rb = (uint32_t)(wn * 32 + ni * 8 + l4) * 64;
                bf[ni][0] = *(const uint32_t*)(Bs + rb + cx[ph * 2]);
                bf[ni][1] = *(const uint32_t*)(Bs + rb + cx[ph * 2 + 1]);
            }
            #pragma unroll
            for (int mi = 0; mi < 4; mi++)
                #pragma unroll
                for (int ni = 0; ni < 4; ni++) {
                    asm volatile(
                        "mma.sync.aligned.m16n8k16.row.col.f32.f16.f16.f32 "
                        "{%0,%1,%2,%3}, {%4,%5,%6,%7}, {%8,%9}, {%0,%1,%2,%3};"
                        : "+f"(acc[mi][ni][0]), "+f"(acc[mi][ni][1]),
                          "+f"(acc[mi][ni][2]), "+f"(acc[mi][ni][3])
                        : "r"(af[mi][0]), "r"(af[mi][1]),
                          "r"(af[mi][2]), "r"(af[mi][3]),
                          "r"(bf[ni][0]), "r"(bf[ni][1]));
                }
        }
        // consumer done with this buffer: one arrive per warp
        __syncwarp();
        if (lane == 0) MBAR_ARRIVE(sb + 8 * (S + (ks % S)));

        // producer: refill buffer (ks-1)%S with stage ks+S-1
        if (tid == 0 && ks + S - 1 < NKt) {
            if (ks > 0)
                MBAR_WAIT(sb + 8 * (S + ((ks - 1) % S)), ((ks - 1) / S) & 1);
            issue(ks + S - 1);
        }
    }

    #pragma unroll
    for (int mi = 0; mi < 4; mi++) {
        int row0 = blockIdx.y * 128 + wm * 64 + mi * 16 + l4;
        #pragma unroll
        for (int ni = 0; ni < 4; ni++) {
            int col0 = blockIdx.x * BN + wn * 32 + ni * 8 + 2 * l2;
            float2* p0 = (float2*)(C + (size_t)row0 * N + col0);
            float2* p1 = (float2*)(C + (size_t)(row0 + 8) * N + col0);
            if (acc_flag) {
                float2 v0 = *p0, v1 = *p1;
                v0.x += acc[mi][ni][0]; v0.y += acc[mi][ni][1];
                v1.x += acc[mi][ni][2]; v1.y += acc[mi][ni][3];
                *p0 = v0; *p1 = v1;
            } else {
                *p0 = make_float2(acc[mi][ni][0], acc[mi][ni][1]);
                *p1 = make_float2(acc[mi][ni][2], acc[mi][ni][3]);
            }
        }
    }
}

constexpr int SMEM_BN256 = 1024 + 6 * (8192 + 256 * 64);   // 148480
constexpr int SMEM_BN128 = 1024 + 6 * (8192 + 128 * 64);   // 99328

// ---------------------------------------------------------------------------
// Causal depthwise conv (K=4) + bias + silu; rolling window, 8 t per thread.
// ---------------------------------------------------------------------------
__global__ void conv_silu8_kernel(const float* __restrict__ cw,
                                  const float* __restrict__ cb) {
    int c  = blockIdx.x * 256 + threadIdx.x;
    int t0 = blockIdx.y * 8;
    const int stride = 2 * kDi;
    float w0 = cw[c * 4 + 0], w1 = cw[c * 4 + 1];
    float w2 = cw[c * 4 + 2], w3 = cw[c * 4 + 3];
    float b  = cb[c];
    float x0 = (t0 >= 3) ? g_xz[(size_t)(t0 - 3) * stride + c] : 0.f;
    float x1 = (t0 >= 2) ? g_xz[(size_t)(t0 - 2) * stride + c] : 0.f;
    float x2 = (t0 >= 1) ? g_xz[(size_t)(t0 - 1) * stride + c] : 0.f;
    #pragma unroll
    for (int i = 0; i < 8; i++) {
        float cur = g_xz[(size_t)(t0 + i) * stride + c];
        float s = b + w0 * x0 + w1 * x1 + w2 * x2 + w3 * cur;
        g_u[(size_t)(t0 + i) * kDi + c] = s / (1.f + __expf(-s));
        x0 = x1; x1 = x2; x2 = cur;
    }
}

// ---------------------------------------------------------------------------
// x_proj, 8 tokens per block: u rows staged in smem, W streamed once/block.
// ---------------------------------------------------------------------------
constexpr int XP_SMEM = 8 * kDi * 4;   // 65536

__global__ __launch_bounds__(256)
void xproj8_kernel(const float* __restrict__ W) {
    extern __shared__ float su[];      // [8][2048]
    int t0 = blockIdx.x * 8;
    const float4* usrc = (const float4*)(g_u + (size_t)t0 * kDi);
    for (int i = threadIdx.x; i < 8 * kDi / 4; i += 256)
        ((float4*)su)[i] = usrc[i];
    __syncthreads();

    int warp = threadIdx.x >> 5, lane = threadIdx.x & 31;
    for (int j = warp; j < kXP; j += 8) {
        const float4* wr = (const float4*)(W + (size_t)j * kDi);
        float acc[8];
        #pragma unroll
        for (int r = 0; r < 8; r++) acc[r] = 0.f;
        #pragma unroll 4
        for (int k = lane; k < kDi / 4; k += 32) {
            float4 bv = wr[k];
            #pragma unroll
            for (int r = 0; r < 8; r++) {
                float4 a = ((const float4*)(su + r * kDi))[k];
                acc[r] += a.x * bv.x + a.y * bv.y + a.z * bv.z + a.w * bv.w;
            }
        }
        #pragma unroll
        for (int r = 0; r < 8; r++) {
            float s = acc[r];
            #pragma unroll
            for (int o = 16; o; o >>= 1) s += __shfl_xor_sync(0xffffffffu, s, o);
            if (lane == 0) g_xp[(t0 + r) * kXP + j] = s;
        }
    }
}

// ---------------------------------------------------------------------------
// Selective scan v3 (R15): register-precomputed dA/db, FMA-only recurrence,
// batched smem reduction.
// ---------------------------------------------------------------------------
__global__ __launch_bounds__(128)
void scan3_kernel(const float* __restrict__ A_log,
                  const float* __restrict__ dtw_,
                  const float* __restrict__ dtb_,
                  const float* __restrict__ Dp_) {
    __shared__ float sxp [2][32][32];
    __shared__ float sraw[2][32];
    __shared__ float su_ [2][32][8];
    __shared__ float sz_ [2][32][8];
    __shared__ float sdt [32][8];
    __shared__ float sdtu[32][8];
    __shared__ float szs [32][8];
    __shared__ float sw2 [32][8];
    __shared__ float sp  [32][8][16];

    int tid = threadIdx.x;
    int d0  = blockIdx.x * 8;
    int n   = tid & 15;
    int dgl = tid >> 4;
    int d   = d0 + dgl;
    float a = -expf(A_log[(size_t)d * kNS + n]);

    int dgd = tid & 7;
    float p_dtw = dtw_[d0 + dgd];
    float p_dtb = dtb_[d0 + dgd];
    float p_Dp  = Dp_[d0 + dgd];

    int r0 = (tid + (tid >> 4)) & 15;

    auto issue = [&](int k) {
        int b = k & 1;
        int t0 = k * 32;
        int i = tid >> 2, j0 = (tid & 3) * 8;
        const float* src = g_xp + (size_t)(t0 + i) * kXP + 1 + j0;
        uint32_t dst = smem_u32(&sxp[b][i][j0]);
        #pragma unroll
        for (int jj = 0; jj < 8; jj++) CP4(dst + 4 * jj, src + jj);
        if (tid < 32)
            CP4(smem_u32(&sraw[b][tid]), g_xp + (size_t)(t0 + tid) * kXP);
        #pragma unroll
        for (int q = 0; q < 2; q++) {
            int e = tid + q * 128;
            int i2 = e >> 3, dg = e & 7;
            CP4(smem_u32(&su_[b][i2][dg]),
                g_u + (size_t)(t0 + i2) * kDi + d0 + dg);
            CP4(smem_u32(&sz_[b][i2][dg]),
                g_xz + (size_t)(t0 + i2) * (2 * kDi) + kDi + d0 + dg);
        }
        asm volatile("cp.async.commit_group;" ::: "memory");
    };

    issue(0);

    float h = 0.f;
    for (int k = 0; k < kT / 32; k++) {
        int b = k & 1;
        asm volatile("cp.async.wait_group 0;" ::: "memory");
        __syncthreads();
        if (k + 1 < kT / 32) issue(k + 1);

        #pragma unroll
        for (int q = 0; q < 2; q++) {
            int e = tid + q * 128;
            int i2 = e >> 3;
            float xv = fmaf(sraw[b][i2], p_dtw, p_dtb);
            float dt = (xv > 20.f) ? xv : log1pf(__expf(xv));
            float u  = su_[b][i2][dgd];
            float z  = sz_[b][i2][dgd];
            float zs = z / (1.f + __expf(-z));
            sdt [i2][dgd] = dt;
            sdtu[i2][dgd] = dt * u;
            szs [i2][dgd] = zs;
            sw2 [i2][dgd] = u * p_Dp * zs;
        }
        __syncthreads();

        float rdA[32], rdb[32], rC[32];
        #pragma unroll
        for (int i = 0; i < 32; i++) {
            rdA[i] = __expf(sdt[i][dgl] * a);
            rdb[i] = sdtu[i][dgl] * sxp[b][i][n];
            rC[i]  = sxp[b][i][16 + n];
        }

        #pragma unroll
        for (int i = 0; i < 32; i++) {
            h = fmaf(rdA[i], h, rdb[i]);
            sp[i][dgl][n] = h * rC[i];
        }
        __syncthreads();

        int tbase = k * 32;
        #pragma unroll
        for (int q = 0; q < 2; q++) {
            int e = tid + q * 128;
            int i = e >> 3, dg = e & 7;
            float s = 0.f;
            #pragma unroll
            for (int kk = 0; kk < 16; kk++)
                s += sp[i][dg][(r0 + kk) & 15];
            float y = fmaf(s, szs[i][dg], sw2[i][dg]);
            int t = tbase + i;
            int dd = d0 + dg;
            int kbq = dd >> 5, colq = dd & 31;
            int tb = t >> 7, r = t & 127;
            size_t off = ((size_t)(tb * (kDi >> 5) + kbq) * 8192) +
                         (uint32_t)((r * 64 + colq * 2) ^ ((r & 7) << 3));
            *(__half*)((char*)g_ygh + off) = __float2half_rn(y);
        }
        __syncthreads();
    }
}

// ---------------------------------------------------------------------------
extern "C" void kernel_launch(void* const* d_in, const int* in_sizes, int n_in,
                              void* d_out, int out_size) {
    const int*   idx        = (const int*)  d_in[0];
    const float* emb        = (const float*)d_in[1];
    const float* norm_w     = (const float*)d_in[2];
    const float* in_proj_w  = (const float*)d_in[3];
    const float* conv_w     = (const float*)d_in[4];
    const float* conv_b     = (const float*)d_in[5];
    const float* x_proj_w   = (const float*)d_in[6];
    const float* dt_proj_w  = (const float*)d_in[7];
    const float* dt_proj_b  = (const float*)d_in[8];
    const float* A_log      = (const float*)d_in[9];
    const float* D_param    = (const float*)d_in[10];
    const float* out_proj_w = (const float*)d_in[11];
    const float* norm_f_w   = (const float*)d_in[12];
    float* out = (float*)d_out;

    float *x, *xz;
    __half *xnh, *ygh, *wh_in, *wh_out, *embh;
    cudaGetSymbolAddress((void**)&x,      g_x);
    cudaGetSymbolAddress((void**)&xnh,    g_xnh);
    cudaGetSymbolAddress((void**)&xz,     g_xz);
    cudaGetSymbolAddress((void**)&ygh,    g_ygh);
    cudaGetSymbolAddress((void**)&wh_in,  g_wh_in);
    cudaGetSymbolAddress((void**)&wh_out, g_wh_out);
    cudaGetSymbolAddress((void**)&embh,   g_embh);

    cudaFuncSetAttribute(gemm_bulk<256, 512>,
                         cudaFuncAttributeMaxDynamicSharedMemorySize, SMEM_BN256);
    cudaFuncSetAttribute(gemm_bulk<128, 256>,
                         cudaFuncAttributeMaxDynamicSharedMemorySize, SMEM_BN128);
    cudaFuncSetAttribute(xproj8_kernel,
                         cudaFuncAttributeMaxDynamicSharedMemorySize, XP_SMEM);

    long n1 = (long)kNL * 2 * kDi * kDm / 4;
    long n2 = (long)kNL * kDm * kDi / 4;
    long n3 = (long)kV * kDm / 4;

    // Launch order: gemm_bulk<256> in slot 4 for the ncu capture window.
    pack_w_kernel<256><<<(int)((n1 + 255) / 256), 256>>>(in_proj_w,  wh_in,
                                                         kNL * 2 * kDi, kDm);   // 1
    embed_kernel<<<kT, 256>>>(idx, emb);                                        // 2
    rmsnorm_kernel<<<kT, 256>>>(x, norm_w, xnh);                                // 3
    gemm_bulk<256, 512><<<dim3(2 * kDi / 256, kT / 128), 512, SMEM_BN256>>>(    // 4
        xnh, wh_in, xz, kT, 2 * kDi, kDm, 0);
    pack_w_kernel<128><<<(int)((n2 + 255) / 256), 256>>>(out_proj_w, wh_out,
                                                         kNL * kDm, kDi);       // 5
    pack_w_kernel<256><<<(int)((n3 + 255) / 256), 256>>>(emb,        embh,
                                                         kV, kDm);              // 6

    for (int l = 0; l < kNL; l++) {
        if (l > 0) {
            rmsnorm_kernel<<<kT, 256>>>(x, norm_w + (size_t)l * kDm, xnh);
            gemm_bulk<256, 512><<<dim3(2 * kDi / 256, kT / 128), 512, SMEM_BN256>>>(
                xnh, wh_in + (size_t)l * 2 * kDi * kDm, xz, kT, 2 * kDi, kDm, 0);
        }
        conv_silu8_kernel<<<dim3(kDi / 256, kT / 8), 256>>>(
            conv_w + (size_t)l * kDi * 4, conv_b + (size_t)l * kDi);
        xproj8_kernel<<<kT / 8, 256, XP_SMEM>>>(x_proj_w + (size_t)l * kXP * kDi);
        scan3_kernel<<<kDi / 8, 128>>>(
            A_log + (size_t)l * kDi * kNS,
            dt_proj_w + (size_t)l * kDi,
            dt_proj_b + (size_t)l * kDi,
            D_param + (size_t)l * kDi);
        gemm_bulk<128, 256><<<dim3(kDm / 128, kT / 128), 256, SMEM_BN128>>>(
            ygh, wh_out + (size_t)l * kDm * kDi, x, kT, kDm, kDi, 1);
    }

    rmsnorm_kernel<<<kT, 256>>>(x, norm_f_w, xnh);
    gemm_bulk<256, 512><<<dim3(kV / 256, kT / 128), 512, SMEM_BN256>>>(
        xnh, embh, out, kT, kV, kDm, 0);
}

// round 17
// speedup vs baseline: 4.8946x; 1.0310x over previous
#include <cuda_runtime.h>
#include <cuda_fp16.h>
#include <math.h>
#include <stdint.h>

constexpr int kT  = 2048;
constexpr int kDm = 1024;
constexpr int kDi = 2048;
constexpr int kNL = 4;
constexpr int kNS = 16;
constexpr int kV  = 32000;
constexpr int kXP = 33;

// Packed fp16 tiles: R rows x 32 halves (64B rows), 16B-granularity swizzle:
// byte off(r, col) = r*64 + (((col>>3) ^ ((r>>1)&3)) << 4) + (col&7)*2
__device__ float  g_x  [kT * kDm];
__device__ __align__(16) __half g_xnh[kT * kDm];
__device__ float  g_xz [kT * 2 * kDi];
__device__ float  g_u  [kT * kDi];
__device__ float  g_xp [kT * kXP];
__device__ __align__(16) __half g_ygh[kT * kDi];
__device__ __align__(16) __half g_wh_in [kNL * 2 * kDi * kDm];
__device__ __align__(16) __half g_wh_out[kNL * kDm * kDi];
__device__ __align__(16) __half g_embh  [kV * kDm];

__device__ __forceinline__ uint32_t smem_u32(const void* p) {
    uint32_t a;
    asm("{ .reg .u64 t; cvta.to.shared.u64 t, %1; cvt.u32.u64 %0, t; }"
        : "=r"(a) : "l"(p));
    return a;
}
#define MBAR_INIT(a, n) \
    asm volatile("mbarrier.init.shared.b64 [%0], %1;" :: "r"(a), "r"(n) : "memory")
#define MBAR_EXPECT_TX(a, tx) \
    asm volatile("mbarrier.arrive.expect_tx.shared.b64 _, [%0], %1;" \
                 :: "r"(a), "r"(tx) : "memory")
#define MBAR_ARRIVE(a) \
    asm volatile("mbarrier.arrive.shared.b64 _, [%0];" :: "r"(a) : "memory")
#define MBAR_WAIT(a, ph) do {                                                \
    asm volatile(                                                            \
        "{\n\t.reg .pred P;\n"                                               \
        "W%=:\n\t"                                                           \
        "mbarrier.try_wait.parity.acquire.cta.shared::cta.b64 P, [%0], %1, 0x989680;\n\t" \
        "@P bra.uni D%=;\n\t"                                                \
        "bra.uni W%=;\n"                                                     \
        "D%=:\n\t}"                                                          \
        :: "r"(a), "r"(ph) : "memory");                                      \
} while (0)
#define BULK_LD(dst, src, bytes, bar) \
    asm volatile("cp.async.bulk.shared::cluster.global.mbarrier::complete_tx::bytes " \
                 "[%0], [%1], %2, [%3];" \
                 :: "r"(dst), "l"(src), "r"(bytes), "r"(bar) : "memory")
#define CP4(dst, src) \
    asm volatile("cp.async.ca.shared.global [%0], [%1], 4;" \
                 :: "r"(dst), "l"(src) : "memory")
#define LDSM4(r0, r1, r2, r3, addr) \
    asm volatile("ldmatrix.sync.aligned.m8n8.x4.shared.b16 {%0,%1,%2,%3}, [%4];" \
                 : "=r"(r0), "=r"(r1), "=r"(r2), "=r"(r3) : "r"(addr))
#define LDSM2(r0, r1, addr) \
    asm volatile("ldmatrix.sync.aligned.m8n8.x2.shared.b16 {%0,%1}, [%2];" \
                 : "=r"(r0), "=r"(r1) : "r"(addr))

// 16B-granularity swizzled byte offset within a tile row
__device__ __forceinline__ uint32_t sw16(int r, int col) {
    return (uint32_t)(r * 64 + ((((col >> 3) ^ ((r >> 1) & 3)) << 4) +
                                (col & 7) * 2));
}

// ---------------------------------------------------------------------------
// Weight pack: f32 [N,K] row-major -> fp16 tiles [nb][kb][R x 32], sw16.
// ---------------------------------------------------------------------------
template <int R>
__global__ void pack_w_kernel(const float* __restrict__ in,
                              __half* __restrict__ out, int N, int K) {
    long i = (long)blockIdx.x * blockDim.x + threadIdx.x;
    long e = i * 4;
    if (e >= (long)N * K) return;
    int n = (int)(e / K), k = (int)(e % K);
    float4 v = *(const float4*)(in + e);
    int nb = n / R, rr = n % R, kb = k >> 5, col = k & 31;
    int NKt = K >> 5;
    size_t off = ((size_t)(nb * NKt + kb) * (R * 64)) + sw16(rr, col);
    __half2 h0 = __floats2half2_rn(v.x, v.y);
    __half2 h1 = __floats2half2_rn(v.z, v.w);
    uint2 u;
    u.x = *(uint32_t*)&h0; u.y = *(uint32_t*)&h1;
    *(uint2*)((char*)out + off) = u;
}

__global__ void embed_kernel(const int* __restrict__ idx,
                             const float* __restrict__ emb) {
    int t = blockIdx.x;
    int row = idx[t];
    ((float4*)(g_x + (size_t)t * kDm))[threadIdx.x] =
        ((const float4*)(emb + (size_t)row * kDm))[threadIdx.x];
}

__global__ void rmsnorm_kernel(const float* __restrict__ in,
                               const float* __restrict__ w,
                               __half* __restrict__ out) {
    __shared__ float red[8];
    __shared__ float s_scale;
    int t = blockIdx.x;
    float4 v = ((const float4*)(in + (size_t)t * kDm))[threadIdx.x];
    float ss = v.x * v.x + v.y * v.y + v.z * v.z + v.w * v.w;
    #pragma unroll
    for (int o = 16; o; o >>= 1) ss += __shfl_xor_sync(0xffffffffu, ss, o);
    int warp = threadIdx.x >> 5, lane = threadIdx.x & 31;
    if (lane == 0) red[warp] = ss;
    __syncthreads();
    if (threadIdx.x == 0) {
        float s = 0.f;
        #pragma unroll
        for (int i = 0; i < 8; i++) s += red[i];
        s_scale = rsqrtf(s / (float)kDm + 1e-5f);
    }
    __syncthreads();
    float sc = s_scale;
    float4 wv = ((const float4*)w)[threadIdx.x];
    __half2 h0 = __floats2half2_rn(v.x * sc * wv.x, v.y * sc * wv.y);
    __half2 h1 = __floats2half2_rn(v.z * sc * wv.z, v.w * sc * wv.w);
    int d0 = threadIdx.x * 4;
    int tb = t >> 7, r = t & 127, kb = d0 >> 5, col = d0 & 31;
    size_t off = ((size_t)(tb * (kDm >> 5) + kb) * 8192) + sw16(r, col);
    uint2 u;
    u.x = *(uint32_t*)&h0; u.y = *(uint32_t*)&h1;
    *(uint2*)((char*)out + off) = u;
}

// ---------------------------------------------------------------------------
// fp16 mma.sync NT GEMM, bulk-copy S=6 ring, producer/consumer barriers,
// ldmatrix fragment loads (16B swizzle).
// ---------------------------------------------------------------------------
template <int BN, int THREADS>
__global__ __launch_bounds__(THREADS, (BN == 128) ? 2 : 1)
void gemm_bulk(const __half* __restrict__ Ap, const __half* __restrict__ Bp,
               float* __restrict__ C, int M, int N, int K, int acc_flag) {
    constexpr int S  = 6;
    constexpr int SB = 8192 + BN * 64;
    constexpr int WNN = BN / 32;
    constexpr int NW  = THREADS / 32;
    extern __shared__ char sm[];
    uint32_t sb = smem_u32(sm);

    int tid = threadIdx.x, lane = tid & 31, wrp = tid >> 5;
    int wm = wrp / WNN, wn = wrp % WNN;
    int l2 = lane & 3, l4 = lane >> 2;
    int NKt = K >> 5;

    const char* gA = (const char*)Ap + (size_t)blockIdx.y * NKt * 8192;
    const char* gB = (const char*)Bp + (size_t)blockIdx.x * NKt * (BN * 64);

    if (tid == 0) {
        #pragma unroll
        for (int s = 0; s < S; s++) {
            MBAR_INIT(sb + 8 * s, 1);
            MBAR_INIT(sb + 8 * (S + s), NW);
        }
    }
    __syncthreads();

    auto issue = [&](int j) {
        uint32_t bar = sb + 8 * (j % S);
        uint32_t dA  = sb + 1024 + (j % S) * SB;
        MBAR_EXPECT_TX(bar, (uint32_t)SB);
        BULK_LD(dA, gA + (size_t)j * 8192, 8192u, bar);
        BULK_LD(dA + 8192, gB + (size_t)j * (BN * 64), (uint32_t)(BN * 64), bar);
    };
    if (tid == 0) {
        #pragma unroll
        for (int j = 0; j < S - 1; j++)
            if (j < NKt) issue(j);
    }

    // ldmatrix per-thread offsets (stage-invariant)
    int Lm = lane >> 3;        // matrix id 0..3
    int Lr = lane & 7;         // row within matrix
    uint32_t aoff[4][2], boff[4][2];
    #pragma unroll
    for (int mi = 0; mi < 4; mi++) {
        int row = wm * 64 + mi * 16 + (Lm & 1) * 8 + Lr;
        int xr = (row >> 1) & 3;
        #pragma unroll
        for (int ph = 0; ph < 2; ph++)
            aoff[mi][ph] = (uint32_t)(row * 64 +
                           (((2 * ph + (Lm >> 1)) ^ xr) << 4));
    }
    int bsel = (lane >> 3) & 1;
    #pragma unroll
    for (int ni = 0; ni < 4; ni++) {
        int row = wn * 32 + ni * 8 + Lr;
        int xr = (row >> 1) & 3;
        #pragma unroll
        for (int ph = 0; ph < 2; ph++)
            boff[ni][ph] = (uint32_t)(row * 64 +
                           (((2 * ph + bsel) ^ xr) << 4));
    }

    float acc[4][4][4];
    #pragma unroll
    for (int i = 0; i < 4; i++)
        #pragma unroll
        for (int j = 0; j < 4; j++)
            #pragma unroll
            for (int r = 0; r < 4; r++) acc[i][j][r] = 0.f;

    for (int ks = 0; ks < NKt; ks++) {
        MBAR_WAIT(sb + 8 * (ks % S), (ks / S) & 1);

        uint32_t As = sb + 1024 + (ks % S) * SB;
        uint32_t Bs = As + 8192;
        #pragma unroll
        for (int ph = 0; ph < 2; ph++) {
            uint32_t af[4][4];
            uint32_t bf[4][2];
            #pragma unroll
            for (int mi = 0; mi < 4; mi++)
                LDSM4(af[mi][0], af[mi][1], af[mi][2], af[mi][3],
                      As + aoff[mi][ph]);
            #pragma unroll
            for (int ni = 0; ni < 4; ni++)
                LDSM2(bf[ni][0], bf[ni][1], Bs + boff[ni][ph]);
            #pragma unroll
            for (int mi = 0; mi < 4; mi++)
                #pragma unroll
                for (int ni = 0; ni < 4; ni++) {
                    asm volatile(
                        "mma.sync.aligned.m16n8k16.row.col.f32.f16.f16.f32 "
                        "{%0,%1,%2,%3}, {%4,%5,%6,%7}, {%8,%9}, {%0,%1,%2,%3};"
                        : "+f"(acc[mi][ni][0]), "+f"(acc[mi][ni][1]),
                          "+f"(acc[mi][ni][2]), "+f"(acc[mi][ni][3])
                        : "r"(af[mi][0]), "r"(af[mi][1]),
                          "r"(af[mi][2]), "r"(af[mi][3]),
                          "r"(bf[ni][0]), "r"(bf[ni][1]));
                }
        }
        __syncwarp();
        if (lane == 0) MBAR_ARRIVE(sb + 8 * (S + (ks % S)));

        if (tid == 0 && ks + S - 1 < NKt) {
            if (ks > 0)
                MBAR_WAIT(sb + 8 * (S + ((ks - 1) % S)), ((ks - 1) / S) & 1);
            issue(ks + S - 1);
        }
    }

    #pragma unroll
    for (int mi = 0; mi < 4; mi++) {
        int row0 = blockIdx.y * 128 + wm * 64 + mi * 16 + l4;
        #pragma unroll
        for (int ni = 0; ni < 4; ni++) {
            int col0 = blockIdx.x * BN + wn * 32 + ni * 8 + 2 * l2;
            float2* p0 = (float2*)(C + (size_t)row0 * N + col0);
            float2* p1 = (float2*)(C + (size_t)(row0 + 8) * N + col0);
            if (acc_flag) {
                float2 v0 = *p0, v1 = *p1;
                v0.x += acc[mi][ni][0]; v0.y += acc[mi][ni][1];
                v1.x += acc[mi][ni][2]; v1.y += acc[mi][ni][3];
                *p0 = v0; *p1 = v1;
            } else {
                *p0 = make_float2(acc[mi][ni][0], acc[mi][ni][1]);
                *p1 = make_float2(acc[mi][ni][2], acc[mi][ni][3]);
            }
        }
    }
}

constexpr int SMEM_BN256 = 1024 + 6 * (8192 + 256 * 64);   // 148480
constexpr int SMEM_BN128 = 1024 + 6 * (8192 + 128 * 64);   // 99328

// ---------------------------------------------------------------------------
// Causal depthwise conv (K=4) + bias + silu; rolling window, 8 t per thread.
// ---------------------------------------------------------------------------
__global__ void conv_silu8_kernel(const float* __restrict__ cw,
                                  const float* __restrict__ cb) {
    int c  = blockIdx.x * 256 + threadIdx.x;
    int t0 = blockIdx.y * 8;
    const int stride = 2 * kDi;
    float w0 = cw[c * 4 + 0], w1 = cw[c * 4 + 1];
    float w2 = cw[c * 4 + 2], w3 = cw[c * 4 + 3];
    float b  = cb[c];
    float x0 = (t0 >= 3) ? g_xz[(size_t)(t0 - 3) * stride + c] : 0.f;
    float x1 = (t0 >= 2) ? g_xz[(size_t)(t0 - 2) * stride + c] : 0.f;
    float x2 = (t0 >= 1) ? g_xz[(size_t)(t0 - 1) * stride + c] : 0.f;
    #pragma unroll
    for (int i = 0; i < 8; i++) {
        float cur = g_xz[(size_t)(t0 + i) * stride + c];
        float s = b + w0 * x0 + w1 * x1 + w2 * x2 + w3 * cur;
        g_u[(size_t)(t0 + i) * kDi + c] = s / (1.f + __expf(-s));
        x0 = x1; x1 = x2; x2 = cur;
    }
}

// ---------------------------------------------------------------------------
// x_proj, 8 tokens per block.
// ---------------------------------------------------------------------------
constexpr int XP_SMEM = 8 * kDi * 4;   // 65536

__global__ __launch_bounds__(256)
void xproj8_kernel(const float* __restrict__ W) {
    extern __shared__ float su[];
    int t0 = blockIdx.x * 8;
    const float4* usrc = (const float4*)(g_u + (size_t)t0 * kDi);
    for (int i = threadIdx.x; i < 8 * kDi / 4; i += 256)
        ((float4*)su)[i] = usrc[i];
    __syncthreads();

    int warp = threadIdx.x >> 5, lane = threadIdx.x & 31;
    for (int j = warp; j < kXP; j += 8) {
        const float4* wr = (const float4*)(W + (size_t)j * kDi);
        float acc[8];
        #pragma unroll
        for (int r = 0; r < 8; r++) acc[r] = 0.f;
        #pragma unroll 4
        for (int k = lane; k < kDi / 4; k += 32) {
            float4 bv = wr[k];
            #pragma unroll
            for (int r = 0; r < 8; r++) {
                float4 a = ((const float4*)(su + r * kDi))[k];
                acc[r] += a.x * bv.x + a.y * bv.y + a.z * bv.z + a.w * bv.w;
            }
        }
        #pragma unroll
        for (int r = 0; r < 8; r++) {
            float s = acc[r];
            #pragma unroll
            for (int o = 16; o; o >>= 1) s += __shfl_xor_sync(0xffffffffu, s, o);
            if (lane == 0) g_xp[(t0 + r) * kXP + j] = s;
        }
    }
}

// ---------------------------------------------------------------------------
// Selective scan v3 (R15) with sw16 output packing.
// ---------------------------------------------------------------------------
__global__ __launch_bounds__(128)
void scan3_kernel(const float* __restrict__ A_log,
                  const float* __restrict__ dtw_,
                  const float* __restrict__ dtb_,
                  const float* __restrict__ Dp_) {
    __shared__ float sxp [2][32][32];
    __shared__ float sraw[2][32];
    __shared__ float su_ [2][32][8];
    __shared__ float sz_ [2][32][8];
    __shared__ float sdt [32][8];
    __shared__ float sdtu[32][8];
    __shared__ float szs [32][8];
    __shared__ float sw2 [32][8];
    __shared__ float sp  [32][8][16];

    int tid = threadIdx.x;
    int d0  = blockIdx.x * 8;
    int n   = tid & 15;
    int dgl = tid >> 4;
    int d   = d0 + dgl;
    float a = -expf(A_log[(size_t)d * kNS + n]);

    int dgd = tid & 7;
    float p_dtw = dtw_[d0 + dgd];
    float p_dtb = dtb_[d0 + dgd];
    float p_Dp  = Dp_[d0 + dgd];

    int r0 = (tid + (tid >> 4)) & 15;

    auto issue = [&](int k) {
        int b = k & 1;
        int t0 = k * 32;
        int i = tid >> 2, j0 = (tid & 3) * 8;
        const float* src = g_xp + (size_t)(t0 + i) * kXP + 1 + j0;
        uint32_t dst = smem_u32(&sxp[b][i][j0]);
        #pragma unroll
        for (int jj = 0; jj < 8; jj++) CP4(dst + 4 * jj, src + jj);
        if (tid < 32)
            CP4(smem_u32(&sraw[b][tid]), g_xp + (size_t)(t0 + tid) * kXP);
        #pragma unroll
        for (int q = 0; q < 2; q++) {
            int e = tid + q * 128;
            int i2 = e >> 3, dg = e & 7;
            CP4(smem_u32(&su_[b][i2][dg]),
                g_u + (size_t)(t0 + i2) * kDi + d0 + dg);
            CP4(smem_u32(&sz_[b][i2][dg]),
                g_xz + (size_t)(t0 + i2) * (2 * kDi) + kDi + d0 + dg);
        }
        asm volatile("cp.async.commit_group;" ::: "memory");
    };

    issue(0);

    float h = 0.f;
    for (int k = 0; k < kT / 32; k++) {
        int b = k & 1;
        asm volatile("cp.async.wait_group 0;" ::: "memory");
        __syncthreads();
        if (k + 1 < kT / 32) issue(k + 1);

        #pragma unroll
        for (int q = 0; q < 2; q++) {
            int e = tid + q * 128;
            int i2 = e >> 3;
            float xv = fmaf(sraw[b][i2], p_dtw, p_dtb);
            float dt = (xv > 20.f) ? xv : log1pf(__expf(xv));
            float u  = su_[b][i2][dgd];
            float z  = sz_[b][i2][dgd];
            float zs = z / (1.f + __expf(-z));
            sdt [i2][dgd] = dt;
            sdtu[i2][dgd] = dt * u;
            szs [i2][dgd] = zs;
            sw2 [i2][dgd] = u * p_Dp * zs;
        }
        __syncthreads();

        float rdA[32], rdb[32], rC[32];
        #pragma unroll
        for (int i = 0; i < 32; i++) {
            rdA[i] = __expf(sdt[i][dgl] * a);
            rdb[i] = sdtu[i][dgl] * sxp[b][i][n];
            rC[i]  = sxp[b][i][16 + n];
        }

        #pragma unroll
        for (int i = 0; i < 32; i++) {
            h = fmaf(rdA[i], h, rdb[i]);
            sp[i][dgl][n] = h * rC[i];
        }
        __syncthreads();

        int tbase = k * 32;
        #pragma unroll
        for (int q = 0; q < 2; q++) {
            int e = tid + q * 128;
            int i = e >> 3, dg = e & 7;
            float s = 0.f;
            #pragma unroll
            for (int kk = 0; kk < 16; kk++)
                s += sp[i][dg][(r0 + kk) & 15];
            float y = fmaf(s, szs[i][dg], sw2[i][dg]);
            int t = tbase + i;
            int dd = d0 + dg;
            int kbq = dd >> 5, colq = dd & 31;
            int tb = t >> 7, r = t & 127;
            size_t off = ((size_t)(tb * (kDi >> 5) + kbq) * 8192) + sw16(r, colq);
            *(__half*)((char*)g_ygh + off) = __float2half_rn(y);
        }
        __syncthreads();
    }
}

// ---------------------------------------------------------------------------
extern "C" void kernel_launch(void* const* d_in, const int* in_sizes, int n_in,
                              void* d_out, int out_size) {
    const int*   idx        = (const int*)  d_in[0];
    const float* emb        = (const float*)d_in[1];
    const float* norm_w     = (const float*)d_in[2];
    const float* in_proj_w  = (const float*)d_in[3];
    const float* conv_w     = (const float*)d_in[4];
    const float* conv_b     = (const float*)d_in[5];
    const float* x_proj_w   = (const float*)d_in[6];
    const float* dt_proj_w  = (const float*)d_in[7];
    const float* dt_proj_b  = (const float*)d_in[8];
    const float* A_log      = (const float*)d_in[9];
    const float* D_param    = (const float*)d_in[10];
    const float* out_proj_w = (const float*)d_in[11];
    const float* norm_f_w   = (const float*)d_in[12];
    float* out = (float*)d_out;

    float *x, *xz;
    __half *xnh, *ygh, *wh_in, *wh_out, *embh;
    cudaGetSymbolAddress((void**)&x,      g_x);
    cudaGetSymbolAddress((void**)&xnh,    g_xnh);
    cudaGetSymbolAddress((void**)&xz,     g_xz);
    cudaGetSymbolAddress((void**)&ygh,    g_ygh);
    cudaGetSymbolAddress((void**)&wh_in,  g_wh_in);
    cudaGetSymbolAddress((void**)&wh_out, g_wh_out);
    cudaGetSymbolAddress((void**)&embh,   g_embh);

    cudaFuncSetAttribute(gemm_bulk<256, 512>,
                         cudaFuncAttributeMaxDynamicSharedMemorySize, SMEM_BN256);
    cudaFuncSetAttribute(gemm_bulk<128, 256>,
                         cudaFuncAttributeMaxDynamicSharedMemorySize, SMEM_BN128);
    cudaFuncSetAttribute(xproj8_kernel,
                         cudaFuncAttributeMaxDynamicSharedMemorySize, XP_SMEM);

    long n1 = (long)kNL * 2 * kDi * kDm / 4;
    long n2 = (long)kNL * kDm * kDi / 4;
    long n3 = (long)kV * kDm / 4;

    // Launch order: gemm_bulk<256> in slot 4 for the ncu capture window.
    pack_w_kernel<256><<<(int)((n1 + 255) / 256), 256>>>(in_proj_w,  wh_in,
                                                         kNL * 2 * kDi, kDm);   // 1
    embed_kernel<<<kT, 256>>>(idx, emb);                                        // 2
    rmsnorm_kernel<<<kT, 256>>>(x, norm_w, xnh);                                // 3
    gemm_bulk<256, 512><<<dim3(2 * kDi / 256, kT / 128), 512, SMEM_BN256>>>(    // 4
        xnh, wh_in, xz, kT, 2 * kDi, kDm, 0);
    pack_w_kernel<128><<<(int)((n2 + 255) / 256), 256>>>(out_proj_w, wh_out,
                                                         kNL * kDm, kDi);       // 5
    pack_w_kernel<256><<<(int)((n3 + 255) / 256), 256>>>(emb,        embh,
                                                         kV, kDm);              // 6

    for (int l = 0; l < kNL; l++) {
        if (l > 0) {
            rmsnorm_kernel<<<kT, 256>>>(x, norm_w + (size_t)l * kDm, xnh);
            gemm_bulk<256, 512><<<dim3(2 * kDi / 256, kT / 128), 512, SMEM_BN256>>>(
                xnh, wh_in + (size_t)l * 2 * kDi * kDm, xz, kT, 2 * kDi, kDm, 0);
        }
        conv_silu8_kernel<<<dim3(kDi / 256, kT / 8), 256>>>(
            conv_w + (size_t)l * kDi * 4, conv_b + (size_t)l * kDi);
        xproj8_kernel<<<kT / 8, 256, XP_SMEM>>>(x_proj_w + (size_t)l * kXP * kDi);
        scan3_kernel<<<kDi / 8, 128>>>(
            A_log + (size_t)l * kDi * kNS,
            dt_proj_w + (size_t)l * kDi,
            dt_proj_b + (size_t)l * kDi,
            D_param + (size_t)l * kDi);
        gemm_bulk<128, 256><<<dim3(kDm / 128, kT / 128), 256, SMEM_BN128>>>(
            ygh, wh_out + (size_t)l * kDm * kDi, x, kT, kDm, kDi, 1);
    }

    rmsnorm_kernel<<<kT, 256>>>(x, norm_f_w, xnh);
    gemm_bulk<256, 512><<<dim3(kV / 256, kT / 128), 512, SMEM_BN256>>>(
        xnh, embh, out, kT, kV, kDm, 0);
}